// round 6
// baseline (speedup 1.0000x reference)
#include <cuda_runtime.h>
#include <cuda_bf16.h>
#include <math.h>

// Problem shape
#define BATCH 512
#define SEQ   256
#define DIM   512
#define NORM  0.044194173824159216f   // 1/sqrt(512)

// Scratch (static __device__ — no dynamic allocation allowed)
__device__ float g_M[DIM * DIM];                         // norm * Wq @ Wk^T
__device__ float g_G[(size_t)BATCH * SEQ * DIM];         // X @ M   (256 MB)
__device__ float g_Y2[(size_t)BATCH * 2 * DIM];          // per-half y contributions

// ---------------------------------------------------------------------------
// helpers
// ---------------------------------------------------------------------------
__device__ __forceinline__ void cp16(float* s, const float* g) {
    unsigned sa = (unsigned)__cvta_generic_to_shared(s);
    asm volatile("cp.async.cg.shared.global [%0], [%1], 16;" :: "r"(sa), "l"(g));
}
#define CP_COMMIT() asm volatile("cp.async.commit_group;")
#define CP_WAIT1()  asm volatile("cp.async.wait_group 1;")

__device__ __forceinline__ void mma_tf32(float c[4],
                                         unsigned a0, unsigned a1, unsigned a2, unsigned a3,
                                         unsigned b0, unsigned b1) {
    asm("mma.sync.aligned.m16n8k8.row.col.f32.tf32.tf32.f32 "
        "{%0,%1,%2,%3}, {%4,%5,%6,%7}, {%8,%9}, {%0,%1,%2,%3};"
        : "+f"(c[0]), "+f"(c[1]), "+f"(c[2]), "+f"(c[3])
        : "r"(a0), "r"(a1), "r"(a2), "r"(a3), "r"(b0), "r"(b1));
}
__device__ __forceinline__ unsigned u32(float f) { return __float_as_uint(f); }

// ---------------------------------------------------------------------------
// Kernel A: M = norm * (Wq @ Wk^T).   (small; scalar)
// ---------------------------------------------------------------------------
__global__ void __launch_bounds__(1024) wqwk_kernel(const float* __restrict__ Wq,
                                                    const float* __restrict__ Wk)
{
    __shared__ float aq[32][33];
    __shared__ float ak[32][33];
    int tx = threadIdx.x, ty = threadIdx.y;
    int row = blockIdx.y * 32 + ty;
    int col = blockIdx.x * 32 + tx;
    float acc = 0.0f;
    for (int kt = 0; kt < DIM; kt += 32) {
        aq[ty][tx] = Wq[row * DIM + kt + tx];
        ak[ty][tx] = Wk[(blockIdx.x * 32 + ty) * DIM + kt + tx];
        __syncthreads();
#pragma unroll
        for (int k = 0; k < 32; k++)
            acc += aq[ty][k] * ak[tx][k];
        __syncthreads();
    }
    g_M[row * DIM + col] = acc * NORM;
}

// ---------------------------------------------------------------------------
// Kernel B: G = Xflat @ M via tf32 mma.sync, cp.async 3-stage pipeline.
// CTA 128x128, BK=16, 256 thr = 8 warps (2x4), warp tile 64x32.
// As stride 20 (conflict-free frags), Bs stride 136 (rows are 128 wide!).
// ---------------------------------------------------------------------------
#define B_STAGE_F (128*20 + 16*136)    // 4736 floats per stage
__global__ void __launch_bounds__(256) gemm_G_kernel(const float* __restrict__ A,
                                                     float* __restrict__ C)
{
    extern __shared__ float smem[];
    int tid  = threadIdx.x;
    int cCol = blockIdx.x;            // 0..3
    int cRow = blockIdx.y;            // 0..1023
    int warp = tid >> 5, lane = tid & 31;
    int wm = warp >> 2, wn = warp & 3;
    int gid = lane >> 2, tig = lane & 3;

    const float* Ab = A + (size_t)cRow * 128 * DIM;
    const float* Mb = g_M + cCol * 128;
    float*       Cb = C + (size_t)cRow * 128 * DIM + cCol * 128;

    int ar = tid >> 1, ak = (tid & 1) * 8;     // A staging: 128 x 16
    int bk = tid >> 4, bn = (tid & 15) * 8;    // B staging: 16 x 128

    float acc[4][4][4];
#pragma unroll
    for (int mt = 0; mt < 4; mt++)
#pragma unroll
        for (int nt = 0; nt < 4; nt++)
#pragma unroll
            for (int r = 0; r < 4; r++) acc[mt][nt][r] = 0.0f;

    auto issue = [&](int s, int kt) {
        float* As = smem + s * B_STAGE_F;
        float* Bs = As + 128 * 20;
        cp16(&As[ar * 20 + ak],      Ab + (size_t)ar * DIM + kt + ak);
        cp16(&As[ar * 20 + ak + 4],  Ab + (size_t)ar * DIM + kt + ak + 4);
        cp16(&Bs[bk * 136 + bn],     Mb + (size_t)(kt + bk) * DIM + bn);
        cp16(&Bs[bk * 136 + bn + 4], Mb + (size_t)(kt + bk) * DIM + bn + 4);
    };

    const int NT = DIM / 16;   // 32
    issue(0, 0);  CP_COMMIT();
    issue(1, 16); CP_COMMIT();

    for (int i = 0; i < NT; i++) {
        CP_WAIT1();
        __syncthreads();
        if (i + 2 < NT) issue((i + 2) % 3, (i + 2) * 16);
        CP_COMMIT();

        const float* As = smem + (i % 3) * B_STAGE_F;
        const float* Bs = As + 128 * 20;
#pragma unroll
        for (int k8 = 0; k8 < 2; k8++) {
            int kb = k8 * 8;
            unsigned af[4][4];
#pragma unroll
            for (int mt = 0; mt < 4; mt++) {
                int row = wm * 64 + mt * 16 + gid;
                af[mt][0] = u32(As[row * 20 + kb + tig]);
                af[mt][1] = u32(As[(row + 8) * 20 + kb + tig]);
                af[mt][2] = u32(As[row * 20 + kb + tig + 4]);
                af[mt][3] = u32(As[(row + 8) * 20 + kb + tig + 4]);
            }
            unsigned bf[4][2];
#pragma unroll
            for (int nt = 0; nt < 4; nt++) {
                int col = wn * 32 + nt * 8 + gid;
                bf[nt][0] = u32(Bs[(kb + tig) * 136 + col]);
                bf[nt][1] = u32(Bs[(kb + tig + 4) * 136 + col]);
            }
#pragma unroll
            for (int mt = 0; mt < 4; mt++)
#pragma unroll
                for (int nt = 0; nt < 4; nt++)
                    mma_tf32(acc[mt][nt], af[mt][0], af[mt][1], af[mt][2], af[mt][3],
                             bf[nt][0], bf[nt][1]);
        }
    }

#pragma unroll
    for (int mt = 0; mt < 4; mt++)
#pragma unroll
        for (int nt = 0; nt < 4; nt++) {
            int r = wm * 64 + mt * 16 + gid;
            int c = wn * 32 + nt * 8 + 2 * tig;
            *(float2*)(Cb + (size_t)r * DIM + c) =
                make_float2(acc[mt][nt][0], acc[mt][nt][1]);
            *(float2*)(Cb + (size_t)(r + 8) * DIM + c) =
                make_float2(acc[mt][nt][2], acc[mt][nt][3]);
        }
}

// ---------------------------------------------------------------------------
// Kernel C: per (batch, half): S = G_half @ X_b^T (tf32 mma, cp.async 3-stage),
// row softmax, colsum(attn) -> w, y = w @ X_b.
// 512 thr = 16 warps (4x4), warp tile 32x64 over S[128x256].
// Gs[128][20] and Xs[256][20] (natural row-major, 16-wide rows), conflict-free.
// ---------------------------------------------------------------------------
#define C_STAGE_F (128*20 + 256*20)    // 7680 floats per stage
__global__ void __launch_bounds__(512) attn_kernel(const float* __restrict__ X,
                                                   float* __restrict__ Y2)
{
    extern __shared__ float smem[];
    float* red  = smem + 3 * C_STAGE_F;        // [128][4]
    float* wcol = red + 128 * 4;               // [4][256]
    float* w_s  = wcol + 4 * 256;              // [256]

    int bx   = blockIdx.x;         // 0..1023
    int b    = bx >> 1;
    int half = bx & 1;
    int tid  = threadIdx.x;
    int warp = tid >> 5, lane = tid & 31;
    int wm = warp >> 2, wn = warp & 3;   // 4 x 4
    int gid = lane >> 2, tig = lane & 3;

    const float* Gb = g_G + ((size_t)b * SEQ + half * 128) * DIM;
    const float* Xb = X + (size_t)b * SEQ * DIM;

    int gr = tid >> 2, gk = (tid & 3) * 4;     // G staging: 128 x 16
    int xm = tid >> 1, xk = (tid & 1) * 8;     // X staging: 256 x 16

    float acc[2][8][4];
#pragma unroll
    for (int mt = 0; mt < 2; mt++)
#pragma unroll
        for (int nt = 0; nt < 8; nt++)
#pragma unroll
            for (int r = 0; r < 4; r++) acc[mt][nt][r] = 0.0f;

    auto issue = [&](int s, int kt) {
        float* Gs = smem + s * C_STAGE_F;
        float* Xs = Gs + 128 * 20;
        cp16(&Gs[gr * 20 + gk],     Gb + (size_t)gr * DIM + kt + gk);
        cp16(&Xs[xm * 20 + xk],     Xb + (size_t)xm * DIM + kt + xk);
        cp16(&Xs[xm * 20 + xk + 4], Xb + (size_t)xm * DIM + kt + xk + 4);
    };

    const int NT = DIM / 16;   // 32
    issue(0, 0);  CP_COMMIT();
    issue(1, 16); CP_COMMIT();

    for (int i = 0; i < NT; i++) {
        CP_WAIT1();
        __syncthreads();
        if (i + 2 < NT) issue((i + 2) % 3, (i + 2) * 16);
        CP_COMMIT();

        const float* Gs = smem + (i % 3) * C_STAGE_F;
        const float* Xs = Gs + 128 * 20;
#pragma unroll
        for (int k8 = 0; k8 < 2; k8++) {
            int kb = k8 * 8;
            unsigned af[2][4];
#pragma unroll
            for (int mt = 0; mt < 2; mt++) {
                int row = wm * 32 + mt * 16 + gid;
                af[mt][0] = u32(Gs[row * 20 + kb + tig]);
                af[mt][1] = u32(Gs[(row + 8) * 20 + kb + tig]);
                af[mt][2] = u32(Gs[row * 20 + kb + tig + 4]);
                af[mt][3] = u32(Gs[(row + 8) * 20 + kb + tig + 4]);
            }
            unsigned bf[8][2];
#pragma unroll
            for (int nt = 0; nt < 8; nt++) {
                int col = wn * 64 + nt * 8 + gid;
                bf[nt][0] = u32(Xs[col * 20 + kb + tig]);
                bf[nt][1] = u32(Xs[col * 20 + kb + tig + 4]);
            }
#pragma unroll
            for (int mt = 0; mt < 2; mt++)
#pragma unroll
                for (int nt = 0; nt < 8; nt++)
                    mma_tf32(acc[mt][nt], af[mt][0], af[mt][1], af[mt][2], af[mt][3],
                             bf[nt][0], bf[nt][1]);
        }
    }
    __syncthreads();

    // ---------------- softmax epilogue ----------------
    // Pass 1: row max
    float rm[2][2];
#pragma unroll
    for (int mt = 0; mt < 2; mt++) {
        float m0 = -1e30f, m1 = -1e30f;
#pragma unroll
        for (int nt = 0; nt < 8; nt++) {
            m0 = fmaxf(m0, fmaxf(acc[mt][nt][0], acc[mt][nt][1]));
            m1 = fmaxf(m1, fmaxf(acc[mt][nt][2], acc[mt][nt][3]));
        }
        m0 = fmaxf(m0, __shfl_xor_sync(0xffffffffu, m0, 1));
        m0 = fmaxf(m0, __shfl_xor_sync(0xffffffffu, m0, 2));
        m1 = fmaxf(m1, __shfl_xor_sync(0xffffffffu, m1, 1));
        m1 = fmaxf(m1, __shfl_xor_sync(0xffffffffu, m1, 2));
        rm[mt][0] = m0; rm[mt][1] = m1;
    }
    if (tig == 0) {
#pragma unroll
        for (int mt = 0; mt < 2; mt++) {
            red[(wm * 32 + mt * 16 + gid) * 4 + wn]     = rm[mt][0];
            red[(wm * 32 + mt * 16 + gid + 8) * 4 + wn] = rm[mt][1];
        }
    }
    __syncthreads();
#pragma unroll
    for (int mt = 0; mt < 2; mt++) {
        int r0 = (wm * 32 + mt * 16 + gid) * 4;
        int r1 = r0 + 32;
        rm[mt][0] = fmaxf(fmaxf(red[r0], red[r0 + 1]), fmaxf(red[r0 + 2], red[r0 + 3]));
        rm[mt][1] = fmaxf(fmaxf(red[r1], red[r1 + 1]), fmaxf(red[r1 + 2], red[r1 + 3]));
    }
    __syncthreads();

    // Pass 2: exp + row sum
    float rs[2][2];
#pragma unroll
    for (int mt = 0; mt < 2; mt++) {
        float s0 = 0.0f, s1 = 0.0f;
#pragma unroll
        for (int nt = 0; nt < 8; nt++) {
            acc[mt][nt][0] = __expf(acc[mt][nt][0] - rm[mt][0]);
            acc[mt][nt][1] = __expf(acc[mt][nt][1] - rm[mt][0]);
            acc[mt][nt][2] = __expf(acc[mt][nt][2] - rm[mt][1]);
            acc[mt][nt][3] = __expf(acc[mt][nt][3] - rm[mt][1]);
            s0 += acc[mt][nt][0] + acc[mt][nt][1];
            s1 += acc[mt][nt][2] + acc[mt][nt][3];
        }
        s0 += __shfl_xor_sync(0xffffffffu, s0, 1);
        s0 += __shfl_xor_sync(0xffffffffu, s0, 2);
        s1 += __shfl_xor_sync(0xffffffffu, s1, 1);
        s1 += __shfl_xor_sync(0xffffffffu, s1, 2);
        rs[mt][0] = s0; rs[mt][1] = s1;
    }
    if (tig == 0) {
#pragma unroll
        for (int mt = 0; mt < 2; mt++) {
            red[(wm * 32 + mt * 16 + gid) * 4 + wn]     = rs[mt][0];
            red[(wm * 32 + mt * 16 + gid + 8) * 4 + wn] = rs[mt][1];
        }
    }
    __syncthreads();
#pragma unroll
    for (int mt = 0; mt < 2; mt++) {
        int r0 = (wm * 32 + mt * 16 + gid) * 4;
        int r1 = r0 + 32;
        rs[mt][0] = 1.0f / (red[r0] + red[r0 + 1] + red[r0 + 2] + red[r0 + 3]);
        rs[mt][1] = 1.0f / (red[r1] + red[r1 + 1] + red[r1 + 2] + red[r1 + 3]);
    }

    // normalize + per-thread column partials
    float cp[8][2];
#pragma unroll
    for (int nt = 0; nt < 8; nt++) {
        cp[nt][0] = acc[0][nt][0] * rs[0][0] + acc[0][nt][2] * rs[0][1]
                  + acc[1][nt][0] * rs[1][0] + acc[1][nt][2] * rs[1][1];
        cp[nt][1] = acc[0][nt][1] * rs[0][0] + acc[0][nt][3] * rs[0][1]
                  + acc[1][nt][1] * rs[1][0] + acc[1][nt][3] * rs[1][1];
    }
#pragma unroll
    for (int nt = 0; nt < 8; nt++) {
#pragma unroll
        for (int o = 4; o < 32; o <<= 1) {
            cp[nt][0] += __shfl_xor_sync(0xffffffffu, cp[nt][0], o);
            cp[nt][1] += __shfl_xor_sync(0xffffffffu, cp[nt][1], o);
        }
    }
    if (gid == 0) {
#pragma unroll
        for (int nt = 0; nt < 8; nt++) {
            wcol[wm * 256 + wn * 64 + nt * 8 + 2 * tig]     = cp[nt][0];
            wcol[wm * 256 + wn * 64 + nt * 8 + 2 * tig + 1] = cp[nt][1];
        }
    }
    __syncthreads();
    if (tid < 256)
        w_s[tid] = wcol[tid] + wcol[256 + tid] + wcol[512 + tid] + wcol[768 + tid];
    __syncthreads();

    // y_part[d] = sum_m w_s[m] * X_b[m, d]
    {
        int d = tid;
        float y = 0.0f;
#pragma unroll 4
        for (int m = 0; m < SEQ; m++)
            y = fmaf(w_s[m], Xb[(size_t)m * DIM + d], y);
        Y2[(size_t)bx * DIM + d] = y;
    }
}

// ---------------------------------------------------------------------------
// Kernel D: merged = Y @ Wv, where Y[b] = Y2[2b] + Y2[2b+1]
// ---------------------------------------------------------------------------
__global__ void __launch_bounds__(1024) final_gemm_kernel(const float* __restrict__ Wv,
                                                          float* __restrict__ out)
{
    __shared__ float ys[32][33];
    __shared__ float ws[32][33];
    int tx = threadIdx.x, ty = threadIdx.y;
    int row = blockIdx.y * 32 + ty;      // batch
    int col = blockIdx.x * 32 + tx;      // output dim
    float acc = 0.0f;
    for (int kt = 0; kt < DIM; kt += 32) {
        ys[ty][tx] = g_Y2[(size_t)(2 * row) * DIM + kt + tx] +
                     g_Y2[(size_t)(2 * row + 1) * DIM + kt + tx];
        ws[ty][tx] = Wv[(size_t)(kt + ty) * DIM + col];
        __syncthreads();
#pragma unroll
        for (int k = 0; k < 32; k++)
            acc += ys[ty][k] * ws[k][tx];
        __syncthreads();
    }
    out[(size_t)row * DIM + col] = acc;
}

// ---------------------------------------------------------------------------
// Launch
// ---------------------------------------------------------------------------
extern "C" void kernel_launch(void* const* d_in, const int* in_sizes, int n_in,
                              void* d_out, int out_size)
{
    const float* X  = (const float*)d_in[0];   // [512,256,512]
    const float* Wq = (const float*)d_in[1];   // [512,512]
    const float* Wk = (const float*)d_in[2];
    const float* Wv = (const float*)d_in[3];
    float* out = (float*)d_out;                // [512,512]

    float* G;
    float* Y2;
    cudaGetSymbolAddress((void**)&G,  g_G);
    cudaGetSymbolAddress((void**)&Y2, g_Y2);

    const int smemB = 3 * B_STAGE_F * sizeof(float);                  // ~55.5 KB
    const int smemC = 3 * C_STAGE_F * sizeof(float) + (512 + 1024 + 256) * sizeof(float); // ~97 KB
    cudaFuncSetAttribute(gemm_G_kernel, cudaFuncAttributeMaxDynamicSharedMemorySize, smemB);
    cudaFuncSetAttribute(attn_kernel,   cudaFuncAttributeMaxDynamicSharedMemorySize, smemC);

    // A: M = norm * Wq @ Wk^T
    wqwk_kernel<<<dim3(16, 16), dim3(32, 32)>>>(Wq, Wk);
    // B: G = Xflat @ M  (tf32 tensor cores, cp.async pipeline)
    gemm_G_kernel<<<dim3(4, 1024), 256, smemB>>>(X, G);
    // C: fused scores/softmax/colsum/y per (batch, half)
    attn_kernel<<<1024, 512, smemC>>>(X, Y2);
    // D: merged = (Y2[2b]+Y2[2b+1]) @ Wv
    final_gemm_kernel<<<dim3(16, 16), dim3(32, 32)>>>(Wv, out);
}

// round 7
// speedup vs baseline: 1.4800x; 1.4800x over previous
#include <cuda_runtime.h>
#include <cuda_bf16.h>
#include <math.h>

// Problem shape
#define BATCH 512
#define SEQ   256
#define DIM   512
#define NORM  0.044194173824159216f   // 1/sqrt(512)

// Scratch (static __device__ — no dynamic allocation allowed)
__device__ float g_M[DIM * DIM];                         // norm * Wq @ Wk^T
__device__ float g_G[(size_t)BATCH * SEQ * DIM];         // X @ M   (256 MB)
__device__ float g_Y2[(size_t)BATCH * 2 * DIM];          // per-half y contributions

// ---------------------------------------------------------------------------
// helpers
// ---------------------------------------------------------------------------
__device__ __forceinline__ void cp16(float* s, const float* g) {
    unsigned sa = (unsigned)__cvta_generic_to_shared(s);
    asm volatile("cp.async.cg.shared.global [%0], [%1], 16;" :: "r"(sa), "l"(g));
}
#define CP_COMMIT() asm volatile("cp.async.commit_group;")
#define CP_WAIT1()  asm volatile("cp.async.wait_group 1;")

__device__ __forceinline__ void mma_tf32(float c[4],
                                         unsigned a0, unsigned a1, unsigned a2, unsigned a3,
                                         unsigned b0, unsigned b1) {
    asm("mma.sync.aligned.m16n8k8.row.col.f32.tf32.tf32.f32 "
        "{%0,%1,%2,%3}, {%4,%5,%6,%7}, {%8,%9}, {%0,%1,%2,%3};"
        : "+f"(c[0]), "+f"(c[1]), "+f"(c[2]), "+f"(c[3])
        : "r"(a0), "r"(a1), "r"(a2), "r"(a3), "r"(b0), "r"(b1));
}
__device__ __forceinline__ unsigned u32(float f) { return __float_as_uint(f); }

// ---------------------------------------------------------------------------
// Kernel A: M = norm * (Wq @ Wk^T).   (small; scalar)
// ---------------------------------------------------------------------------
__global__ void __launch_bounds__(1024) wqwk_kernel(const float* __restrict__ Wq,
                                                    const float* __restrict__ Wk)
{
    __shared__ float aq[32][33];
    __shared__ float ak[32][33];
    int tx = threadIdx.x, ty = threadIdx.y;
    int row = blockIdx.y * 32 + ty;
    int col = blockIdx.x * 32 + tx;
    float acc = 0.0f;
    for (int kt = 0; kt < DIM; kt += 32) {
        aq[ty][tx] = Wq[row * DIM + kt + tx];
        ak[ty][tx] = Wk[(blockIdx.x * 32 + ty) * DIM + kt + tx];
        __syncthreads();
#pragma unroll
        for (int k = 0; k < 32; k++)
            acc += aq[ty][k] * ak[tx][k];
        __syncthreads();
    }
    g_M[row * DIM + col] = acc * NORM;
}

// ---------------------------------------------------------------------------
// Kernel B: G = Xflat @ M via tf32 mma.sync, cp.async 3-stage pipeline.
// CTA 128x128, BK=16, 256 thr = 8 warps (2x4), warp tile 64x32.
// As stride 20 (conflict-free frags), Bs stride 136.
// ---------------------------------------------------------------------------
#define B_STAGE_F (128*20 + 16*136)    // 4736 floats per stage
__global__ void __launch_bounds__(256) gemm_G_kernel(const float* __restrict__ A,
                                                     float* __restrict__ C)
{
    extern __shared__ float smem[];
    int tid  = threadIdx.x;
    int cCol = blockIdx.x;            // 0..3
    int cRow = blockIdx.y;            // 0..1023
    int warp = tid >> 5, lane = tid & 31;
    int wm = warp >> 2, wn = warp & 3;
    int gid = lane >> 2, tig = lane & 3;

    const float* Ab = A + (size_t)cRow * 128 * DIM;
    const float* Mb = g_M + cCol * 128;
    float*       Cb = C + (size_t)cRow * 128 * DIM + cCol * 128;

    int ar = tid >> 1, ak = (tid & 1) * 8;     // A staging: 128 x 16
    int bk = tid >> 4, bn = (tid & 15) * 8;    // B staging: 16 x 128

    float acc[4][4][4];
#pragma unroll
    for (int mt = 0; mt < 4; mt++)
#pragma unroll
        for (int nt = 0; nt < 4; nt++)
#pragma unroll
            for (int r = 0; r < 4; r++) acc[mt][nt][r] = 0.0f;

    auto issue = [&](int s, int kt) {
        float* As = smem + s * B_STAGE_F;
        float* Bs = As + 128 * 20;
        cp16(&As[ar * 20 + ak],      Ab + (size_t)ar * DIM + kt + ak);
        cp16(&As[ar * 20 + ak + 4],  Ab + (size_t)ar * DIM + kt + ak + 4);
        cp16(&Bs[bk * 136 + bn],     Mb + (size_t)(kt + bk) * DIM + bn);
        cp16(&Bs[bk * 136 + bn + 4], Mb + (size_t)(kt + bk) * DIM + bn + 4);
    };

    const int NT = DIM / 16;   // 32
    issue(0, 0);  CP_COMMIT();
    issue(1, 16); CP_COMMIT();

    for (int i = 0; i < NT; i++) {
        CP_WAIT1();
        __syncthreads();
        if (i + 2 < NT) issue((i + 2) % 3, (i + 2) * 16);
        CP_COMMIT();

        const float* As = smem + (i % 3) * B_STAGE_F;
        const float* Bs = As + 128 * 20;
#pragma unroll
        for (int k8 = 0; k8 < 2; k8++) {
            int kb = k8 * 8;
            unsigned af[4][4];
#pragma unroll
            for (int mt = 0; mt < 4; mt++) {
                int row = wm * 64 + mt * 16 + gid;
                af[mt][0] = u32(As[row * 20 + kb + tig]);
                af[mt][1] = u32(As[(row + 8) * 20 + kb + tig]);
                af[mt][2] = u32(As[row * 20 + kb + tig + 4]);
                af[mt][3] = u32(As[(row + 8) * 20 + kb + tig + 4]);
            }
            unsigned bf[4][2];
#pragma unroll
            for (int nt = 0; nt < 4; nt++) {
                int col = wn * 32 + nt * 8 + gid;
                bf[nt][0] = u32(Bs[(kb + tig) * 136 + col]);
                bf[nt][1] = u32(Bs[(kb + tig + 4) * 136 + col]);
            }
#pragma unroll
            for (int mt = 0; mt < 4; mt++)
#pragma unroll
                for (int nt = 0; nt < 4; nt++)
                    mma_tf32(acc[mt][nt], af[mt][0], af[mt][1], af[mt][2], af[mt][3],
                             bf[nt][0], bf[nt][1]);
        }
    }

#pragma unroll
    for (int mt = 0; mt < 4; mt++)
#pragma unroll
        for (int nt = 0; nt < 4; nt++) {
            int r = wm * 64 + mt * 16 + gid;
            int c = wn * 32 + nt * 8 + 2 * tig;
            *(float2*)(Cb + (size_t)r * DIM + c) =
                make_float2(acc[mt][nt][0], acc[mt][nt][1]);
            *(float2*)(Cb + (size_t)(r + 8) * DIM + c) =
                make_float2(acc[mt][nt][2], acc[mt][nt][3]);
        }
}

// ---------------------------------------------------------------------------
// Kernel C: per (batch, half): S = G_half @ X_b^T (tf32 mma, cp.async 3-stage),
// row softmax, colsum(attn) -> w, y = w @ X_b.
// 512 thr = 16 warps (4x4), warp tile 32x64 over S[128x256].
// ---------------------------------------------------------------------------
#define C_STAGE_F (128*20 + 256*20)    // 7680 floats per stage
__global__ void __launch_bounds__(512) attn_kernel(const float* __restrict__ X,
                                                   float* __restrict__ Y2)
{
    extern __shared__ float smem[];
    float* red  = smem + 3 * C_STAGE_F;        // [128][4]
    float* wcol = red + 128 * 4;               // [4][256]
    float* w_s  = wcol + 4 * 256;              // [256]

    int bx   = blockIdx.x;         // 0..1023
    int b    = bx >> 1;
    int half = bx & 1;
    int tid  = threadIdx.x;
    int warp = tid >> 5, lane = tid & 31;
    int wm = warp >> 2, wn = warp & 3;   // 4 x 4
    int gid = lane >> 2, tig = lane & 3;

    const float* Gb = g_G + ((size_t)b * SEQ + half * 128) * DIM;
    const float* Xb = X + (size_t)b * SEQ * DIM;

    int gr = tid >> 2, gk = (tid & 3) * 4;     // G staging: 128 x 16
    int xm = tid >> 1, xk = (tid & 1) * 8;     // X staging: 256 x 16

    float acc[2][8][4];
#pragma unroll
    for (int mt = 0; mt < 2; mt++)
#pragma unroll
        for (int nt = 0; nt < 8; nt++)
#pragma unroll
            for (int r = 0; r < 4; r++) acc[mt][nt][r] = 0.0f;

    auto issue = [&](int s, int kt) {
        float* Gs = smem + s * C_STAGE_F;
        float* Xs = Gs + 128 * 20;
        cp16(&Gs[gr * 20 + gk],     Gb + (size_t)gr * DIM + kt + gk);
        cp16(&Xs[xm * 20 + xk],     Xb + (size_t)xm * DIM + kt + xk);
        cp16(&Xs[xm * 20 + xk + 4], Xb + (size_t)xm * DIM + kt + xk + 4);
    };

    const int NT = DIM / 16;   // 32
    issue(0, 0);  CP_COMMIT();
    issue(1, 16); CP_COMMIT();

    for (int i = 0; i < NT; i++) {
        CP_WAIT1();
        __syncthreads();
        if (i + 2 < NT) issue((i + 2) % 3, (i + 2) * 16);
        CP_COMMIT();

        const float* Gs = smem + (i % 3) * C_STAGE_F;
        const float* Xs = Gs + 128 * 20;
#pragma unroll
        for (int k8 = 0; k8 < 2; k8++) {
            int kb = k8 * 8;
            unsigned af[2][4];
#pragma unroll
            for (int mt = 0; mt < 2; mt++) {
                int row = wm * 32 + mt * 16 + gid;
                af[mt][0] = u32(Gs[row * 20 + kb + tig]);
                af[mt][1] = u32(Gs[(row + 8) * 20 + kb + tig]);
                af[mt][2] = u32(Gs[row * 20 + kb + tig + 4]);
                af[mt][3] = u32(Gs[(row + 8) * 20 + kb + tig + 4]);
            }
            unsigned bf[8][2];
#pragma unroll
            for (int nt = 0; nt < 8; nt++) {
                int col = wn * 64 + nt * 8 + gid;
                bf[nt][0] = u32(Xs[col * 20 + kb + tig]);
                bf[nt][1] = u32(Xs[col * 20 + kb + tig + 4]);
            }
#pragma unroll
            for (int mt = 0; mt < 2; mt++)
#pragma unroll
                for (int nt = 0; nt < 8; nt++)
                    mma_tf32(acc[mt][nt], af[mt][0], af[mt][1], af[mt][2], af[mt][3],
                             bf[nt][0], bf[nt][1]);
        }
    }
    __syncthreads();

    // ---------------- softmax epilogue ----------------
    float rm[2][2];
#pragma unroll
    for (int mt = 0; mt < 2; mt++) {
        float m0 = -1e30f, m1 = -1e30f;
#pragma unroll
        for (int nt = 0; nt < 8; nt++) {
            m0 = fmaxf(m0, fmaxf(acc[mt][nt][0], acc[mt][nt][1]));
            m1 = fmaxf(m1, fmaxf(acc[mt][nt][2], acc[mt][nt][3]));
        }
        m0 = fmaxf(m0, __shfl_xor_sync(0xffffffffu, m0, 1));
        m0 = fmaxf(m0, __shfl_xor_sync(0xffffffffu, m0, 2));
        m1 = fmaxf(m1, __shfl_xor_sync(0xffffffffu, m1, 1));
        m1 = fmaxf(m1, __shfl_xor_sync(0xffffffffu, m1, 2));
        rm[mt][0] = m0; rm[mt][1] = m1;
    }
    if (tig == 0) {
#pragma unroll
        for (int mt = 0; mt < 2; mt++) {
            red[(wm * 32 + mt * 16 + gid) * 4 + wn]     = rm[mt][0];
            red[(wm * 32 + mt * 16 + gid + 8) * 4 + wn] = rm[mt][1];
        }
    }
    __syncthreads();
#pragma unroll
    for (int mt = 0; mt < 2; mt++) {
        int r0 = (wm * 32 + mt * 16 + gid) * 4;
        int r1 = r0 + 32;
        rm[mt][0] = fmaxf(fmaxf(red[r0], red[r0 + 1]), fmaxf(red[r0 + 2], red[r0 + 3]));
        rm[mt][1] = fmaxf(fmaxf(red[r1], red[r1 + 1]), fmaxf(red[r1 + 2], red[r1 + 3]));
    }
    __syncthreads();

    float rs[2][2];
#pragma unroll
    for (int mt = 0; mt < 2; mt++) {
        float s0 = 0.0f, s1 = 0.0f;
#pragma unroll
        for (int nt = 0; nt < 8; nt++) {
            acc[mt][nt][0] = __expf(acc[mt][nt][0] - rm[mt][0]);
            acc[mt][nt][1] = __expf(acc[mt][nt][1] - rm[mt][0]);
            acc[mt][nt][2] = __expf(acc[mt][nt][2] - rm[mt][1]);
            acc[mt][nt][3] = __expf(acc[mt][nt][3] - rm[mt][1]);
            s0 += acc[mt][nt][0] + acc[mt][nt][1];
            s1 += acc[mt][nt][2] + acc[mt][nt][3];
        }
        s0 += __shfl_xor_sync(0xffffffffu, s0, 1);
        s0 += __shfl_xor_sync(0xffffffffu, s0, 2);
        s1 += __shfl_xor_sync(0xffffffffu, s1, 1);
        s1 += __shfl_xor_sync(0xffffffffu, s1, 2);
        rs[mt][0] = s0; rs[mt][1] = s1;
    }
    if (tig == 0) {
#pragma unroll
        for (int mt = 0; mt < 2; mt++) {
            red[(wm * 32 + mt * 16 + gid) * 4 + wn]     = rs[mt][0];
            red[(wm * 32 + mt * 16 + gid + 8) * 4 + wn] = rs[mt][1];
        }
    }
    __syncthreads();
#pragma unroll
    for (int mt = 0; mt < 2; mt++) {
        int r0 = (wm * 32 + mt * 16 + gid) * 4;
        int r1 = r0 + 32;
        rs[mt][0] = 1.0f / (red[r0] + red[r0 + 1] + red[r0 + 2] + red[r0 + 3]);
        rs[mt][1] = 1.0f / (red[r1] + red[r1 + 1] + red[r1 + 2] + red[r1 + 3]);
    }

    float cp[8][2];
#pragma unroll
    for (int nt = 0; nt < 8; nt++) {
        cp[nt][0] = acc[0][nt][0] * rs[0][0] + acc[0][nt][2] * rs[0][1]
                  + acc[1][nt][0] * rs[1][0] + acc[1][nt][2] * rs[1][1];
        cp[nt][1] = acc[0][nt][1] * rs[0][0] + acc[0][nt][3] * rs[0][1]
                  + acc[1][nt][1] * rs[1][0] + acc[1][nt][3] * rs[1][1];
    }
#pragma unroll
    for (int nt = 0; nt < 8; nt++) {
#pragma unroll
        for (int o = 4; o < 32; o <<= 1) {
            cp[nt][0] += __shfl_xor_sync(0xffffffffu, cp[nt][0], o);
            cp[nt][1] += __shfl_xor_sync(0xffffffffu, cp[nt][1], o);
        }
    }
    if (gid == 0) {
#pragma unroll
        for (int nt = 0; nt < 8; nt++) {
            wcol[wm * 256 + wn * 64 + nt * 8 + 2 * tig]     = cp[nt][0];
            wcol[wm * 256 + wn * 64 + nt * 8 + 2 * tig + 1] = cp[nt][1];
        }
    }
    __syncthreads();
    if (tid < 256)
        w_s[tid] = wcol[tid] + wcol[256 + tid] + wcol[512 + tid] + wcol[768 + tid];
    __syncthreads();

    // y_part[d] = sum_m w_s[m] * X_b[m, d]
    {
        int d = tid;
        float y = 0.0f;
#pragma unroll 4
        for (int m = 0; m < SEQ; m++)
            y = fmaf(w_s[m], Xb[(size_t)m * DIM + d], y);
        Y2[(size_t)bx * DIM + d] = y;
    }
}

// ---------------------------------------------------------------------------
// Kernel D: merged = Y @ Wv, Y[b] = Y2[2b] + Y2[2b+1].
// 128x128 tile, BK=16, 256 thr, 8x8 microtile (scalar; only 0.27 GF).
// ---------------------------------------------------------------------------
__global__ void __launch_bounds__(256) final_gemm_kernel(const float* __restrict__ Wv,
                                                         float* __restrict__ out)
{
    __shared__ float As[16][132];    // [k][batch]
    __shared__ float Bs[16][132];    // [k][col]
    int tid  = threadIdx.x;
    int cCol = blockIdx.x;           // 0..3
    int cRow = blockIdx.y;           // 0..3

    int ar = tid >> 1, akk = (tid & 1) * 8;   // A staging: 128 rows x 16 k
    int bk = tid >> 4, bn = (tid & 15) * 8;   // B staging: 16 k x 128 cols
    int tr = tid >> 4, tc = tid & 15;

    float acc[8][8];
#pragma unroll
    for (int i = 0; i < 8; i++)
#pragma unroll
        for (int j = 0; j < 8; j++) acc[i][j] = 0.0f;

    int batch0 = cRow * 128;
    for (int kt = 0; kt < DIM; kt += 16) {
        // A: Y[b][k] = Y2[2b][k] + Y2[2b+1][k], stored transposed As[k][b]
        {
            const float* y0 = g_Y2 + (size_t)(2 * (batch0 + ar)) * DIM + kt + akk;
            const float* y1 = y0 + DIM;
            float4 a0 = *(const float4*)y0;
            float4 a1 = *(const float4*)(y0 + 4);
            float4 b0 = *(const float4*)y1;
            float4 b1 = *(const float4*)(y1 + 4);
            As[akk + 0][ar] = a0.x + b0.x;
            As[akk + 1][ar] = a0.y + b0.y;
            As[akk + 2][ar] = a0.z + b0.z;
            As[akk + 3][ar] = a0.w + b0.w;
            As[akk + 4][ar] = a1.x + b1.x;
            As[akk + 5][ar] = a1.y + b1.y;
            As[akk + 6][ar] = a1.z + b1.z;
            As[akk + 7][ar] = a1.w + b1.w;
        }
        // B: Wv rows
        {
            const float* wp = Wv + (size_t)(kt + bk) * DIM + cCol * 128 + bn;
            *(float4*)(&Bs[bk][bn])     = *(const float4*)wp;
            *(float4*)(&Bs[bk][bn + 4]) = *(const float4*)(wp + 4);
        }
        __syncthreads();
#pragma unroll
        for (int k = 0; k < 16; k++) {
            float4 m0 = *(const float4*)(&As[k][tr * 8]);
            float4 m1 = *(const float4*)(&As[k][tr * 8 + 4]);
            float4 n0 = *(const float4*)(&Bs[k][tc * 8]);
            float4 n1 = *(const float4*)(&Bs[k][tc * 8 + 4]);
            float ra[8] = {m0.x, m0.y, m0.z, m0.w, m1.x, m1.y, m1.z, m1.w};
            float rb[8] = {n0.x, n0.y, n0.z, n0.w, n1.x, n1.y, n1.z, n1.w};
#pragma unroll
            for (int i = 0; i < 8; i++)
#pragma unroll
                for (int j = 0; j < 8; j++)
                    acc[i][j] += ra[i] * rb[j];
        }
        __syncthreads();
    }
#pragma unroll
    for (int i = 0; i < 8; i++) {
        float* op = out + (size_t)(batch0 + tr * 8 + i) * DIM + cCol * 128 + tc * 8;
        *(float4*)op       = make_float4(acc[i][0], acc[i][1], acc[i][2], acc[i][3]);
        *(float4*)(op + 4) = make_float4(acc[i][4], acc[i][5], acc[i][6], acc[i][7]);
    }
}

// ---------------------------------------------------------------------------
// Launch
// ---------------------------------------------------------------------------
extern "C" void kernel_launch(void* const* d_in, const int* in_sizes, int n_in,
                              void* d_out, int out_size)
{
    const float* X  = (const float*)d_in[0];   // [512,256,512]
    const float* Wq = (const float*)d_in[1];   // [512,512]
    const float* Wk = (const float*)d_in[2];
    const float* Wv = (const float*)d_in[3];
    float* out = (float*)d_out;                // [512,512]

    float* G;
    float* Y2;
    cudaGetSymbolAddress((void**)&G,  g_G);
    cudaGetSymbolAddress((void**)&Y2, g_Y2);

    const int smemB = 3 * B_STAGE_F * sizeof(float);                  // ~55.5 KB
    const int smemC = 3 * C_STAGE_F * sizeof(float) + (512 + 1024 + 256) * sizeof(float); // ~97 KB
    cudaFuncSetAttribute(gemm_G_kernel, cudaFuncAttributeMaxDynamicSharedMemorySize, smemB);
    cudaFuncSetAttribute(attn_kernel,   cudaFuncAttributeMaxDynamicSharedMemorySize, smemC);

    // A: M = norm * Wq @ Wk^T
    wqwk_kernel<<<dim3(16, 16), dim3(32, 32)>>>(Wq, Wk);
    // B: G = Xflat @ M  (tf32 tensor cores, cp.async pipeline)
    gemm_G_kernel<<<dim3(4, 1024), 256, smemB>>>(X, G);
    // C: fused scores/softmax/colsum/y per (batch, half)
    attn_kernel<<<1024, 512, smemC>>>(X, Y2);
    // D: merged = (Y2[2b]+Y2[2b+1]) @ Wv
    final_gemm_kernel<<<dim3(4, 4), 256>>>(Wv, out);
}

// round 8
// speedup vs baseline: 1.5779x; 1.0661x over previous
#include <cuda_runtime.h>
#include <cuda_bf16.h>
#include <math.h>

// Problem shape
#define BATCH 512
#define SEQ   256
#define DIM   512
#define NORM  0.044194173824159216f   // 1/sqrt(512)

// Scratch (static __device__ — no dynamic allocation allowed)
__device__ float g_M[DIM * DIM];                         // norm * Wq @ Wk^T
__device__ float g_G[(size_t)BATCH * SEQ * DIM];         // X @ M   (256 MB)
__device__ float g_Y2[(size_t)BATCH * 2 * DIM];          // per-half y contributions

// ---------------------------------------------------------------------------
// helpers
// ---------------------------------------------------------------------------
__device__ __forceinline__ void cp16(float* s, const float* g) {
    unsigned sa = (unsigned)__cvta_generic_to_shared(s);
    asm volatile("cp.async.cg.shared.global [%0], [%1], 16;" :: "r"(sa), "l"(g));
}
#define CP_COMMIT() asm volatile("cp.async.commit_group;")
#define CP_WAIT1()  asm volatile("cp.async.wait_group 1;")

__device__ __forceinline__ void mma_tf32(float c[4],
                                         unsigned a0, unsigned a1, unsigned a2, unsigned a3,
                                         unsigned b0, unsigned b1) {
    asm("mma.sync.aligned.m16n8k8.row.col.f32.tf32.tf32.f32 "
        "{%0,%1,%2,%3}, {%4,%5,%6,%7}, {%8,%9}, {%0,%1,%2,%3};"
        : "+f"(c[0]), "+f"(c[1]), "+f"(c[2]), "+f"(c[3])
        : "r"(a0), "r"(a1), "r"(a2), "r"(a3), "r"(b0), "r"(b1));
}
__device__ __forceinline__ unsigned u32(float f) { return __float_as_uint(f); }

// ---------------------------------------------------------------------------
// Kernel A: M = norm * (Wq @ Wk^T).  64x64 tiles, grid 8x8, 256 thr, 4x4 micro
// ---------------------------------------------------------------------------
__global__ void __launch_bounds__(256) wqwk_kernel(const float* __restrict__ Wq,
                                                   const float* __restrict__ Wk)
{
    __shared__ float As[32][68];   // [e][row]
    __shared__ float Bs[32][68];   // [e][col]
    int tid = threadIdx.x;
    int row0 = blockIdx.y * 64;
    int col0 = blockIdx.x * 64;

    int sr = tid >> 2, se = (tid & 3) * 8;   // staging: 64 rows x 32 e
    int tr = tid >> 4, tc = tid & 15;

    float acc[4][4];
#pragma unroll
    for (int i = 0; i < 4; i++)
#pragma unroll
        for (int j = 0; j < 4; j++) acc[i][j] = 0.0f;

    for (int kt = 0; kt < DIM; kt += 32) {
        float4 q0 = *(const float4*)(Wq + (size_t)(row0 + sr) * DIM + kt + se);
        float4 q1 = *(const float4*)(Wq + (size_t)(row0 + sr) * DIM + kt + se + 4);
        float4 k0 = *(const float4*)(Wk + (size_t)(col0 + sr) * DIM + kt + se);
        float4 k1 = *(const float4*)(Wk + (size_t)(col0 + sr) * DIM + kt + se + 4);
        As[se + 0][sr] = q0.x; As[se + 1][sr] = q0.y;
        As[se + 2][sr] = q0.z; As[se + 3][sr] = q0.w;
        As[se + 4][sr] = q1.x; As[se + 5][sr] = q1.y;
        As[se + 6][sr] = q1.z; As[se + 7][sr] = q1.w;
        Bs[se + 0][sr] = k0.x; Bs[se + 1][sr] = k0.y;
        Bs[se + 2][sr] = k0.z; Bs[se + 3][sr] = k0.w;
        Bs[se + 4][sr] = k1.x; Bs[se + 5][sr] = k1.y;
        Bs[se + 6][sr] = k1.z; Bs[se + 7][sr] = k1.w;
        __syncthreads();
#pragma unroll
        for (int k = 0; k < 32; k++) {
            float4 ra = *(const float4*)(&As[k][tr * 4]);
            float4 rb = *(const float4*)(&Bs[k][tc * 4]);
            float a[4] = {ra.x, ra.y, ra.z, ra.w};
            float b[4] = {rb.x, rb.y, rb.z, rb.w};
#pragma unroll
            for (int i = 0; i < 4; i++)
#pragma unroll
                for (int j = 0; j < 4; j++)
                    acc[i][j] += a[i] * b[j];
        }
        __syncthreads();
    }
#pragma unroll
    for (int i = 0; i < 4; i++) {
        float* mp = g_M + (size_t)(row0 + tr * 4 + i) * DIM + col0 + tc * 4;
        *(float4*)mp = make_float4(acc[i][0] * NORM, acc[i][1] * NORM,
                                   acc[i][2] * NORM, acc[i][3] * NORM);
    }
}

// ---------------------------------------------------------------------------
// Kernel B: G = Xflat @ M via tf32 mma.sync, cp.async 3-stage pipeline.
// CTA 128x128, BK=16, 256 thr = 8 warps (2x4), warp tile 64x32.
// As stride 20 (conflict-free frags), Bs stride 136.
// ---------------------------------------------------------------------------
#define B_STAGE_F (128*20 + 16*136)    // 4736 floats per stage
__global__ void __launch_bounds__(256) gemm_G_kernel(const float* __restrict__ A,
                                                     float* __restrict__ C)
{
    extern __shared__ float smem[];
    int tid  = threadIdx.x;
    int cCol = blockIdx.x;            // 0..3
    int cRow = blockIdx.y;            // 0..1023
    int warp = tid >> 5, lane = tid & 31;
    int wm = warp >> 2, wn = warp & 3;
    int gid = lane >> 2, tig = lane & 3;

    const float* Ab = A + (size_t)cRow * 128 * DIM;
    const float* Mb = g_M + cCol * 128;
    float*       Cb = C + (size_t)cRow * 128 * DIM + cCol * 128;

    int ar = tid >> 1, ak = (tid & 1) * 8;     // A staging: 128 x 16
    int bk = tid >> 4, bn = (tid & 15) * 8;    // B staging: 16 x 128

    float acc[4][4][4];
#pragma unroll
    for (int mt = 0; mt < 4; mt++)
#pragma unroll
        for (int nt = 0; nt < 4; nt++)
#pragma unroll
            for (int r = 0; r < 4; r++) acc[mt][nt][r] = 0.0f;

    auto issue = [&](int s, int kt) {
        float* As = smem + s * B_STAGE_F;
        float* Bs = As + 128 * 20;
        cp16(&As[ar * 20 + ak],      Ab + (size_t)ar * DIM + kt + ak);
        cp16(&As[ar * 20 + ak + 4],  Ab + (size_t)ar * DIM + kt + ak + 4);
        cp16(&Bs[bk * 136 + bn],     Mb + (size_t)(kt + bk) * DIM + bn);
        cp16(&Bs[bk * 136 + bn + 4], Mb + (size_t)(kt + bk) * DIM + bn + 4);
    };

    const int NT = DIM / 16;   // 32
    issue(0, 0);  CP_COMMIT();
    issue(1, 16); CP_COMMIT();

    for (int i = 0; i < NT; i++) {
        CP_WAIT1();
        __syncthreads();
        if (i + 2 < NT) issue((i + 2) % 3, (i + 2) * 16);
        CP_COMMIT();

        const float* As = smem + (i % 3) * B_STAGE_F;
        const float* Bs = As + 128 * 20;
#pragma unroll
        for (int k8 = 0; k8 < 2; k8++) {
            int kb = k8 * 8;
            unsigned af[4][4];
#pragma unroll
            for (int mt = 0; mt < 4; mt++) {
                int row = wm * 64 + mt * 16 + gid;
                af[mt][0] = u32(As[row * 20 + kb + tig]);
                af[mt][1] = u32(As[(row + 8) * 20 + kb + tig]);
                af[mt][2] = u32(As[row * 20 + kb + tig + 4]);
                af[mt][3] = u32(As[(row + 8) * 20 + kb + tig + 4]);
            }
            unsigned bf[4][2];
#pragma unroll
            for (int nt = 0; nt < 4; nt++) {
                int col = wn * 32 + nt * 8 + gid;
                bf[nt][0] = u32(Bs[(kb + tig) * 136 + col]);
                bf[nt][1] = u32(Bs[(kb + tig + 4) * 136 + col]);
            }
#pragma unroll
            for (int mt = 0; mt < 4; mt++)
#pragma unroll
                for (int nt = 0; nt < 4; nt++)
                    mma_tf32(acc[mt][nt], af[mt][0], af[mt][1], af[mt][2], af[mt][3],
                             bf[nt][0], bf[nt][1]);
        }
    }

#pragma unroll
    for (int mt = 0; mt < 4; mt++)
#pragma unroll
        for (int nt = 0; nt < 4; nt++) {
            int r = wm * 64 + mt * 16 + gid;
            int c = wn * 32 + nt * 8 + 2 * tig;
            *(float2*)(Cb + (size_t)r * DIM + c) =
                make_float2(acc[mt][nt][0], acc[mt][nt][1]);
            *(float2*)(Cb + (size_t)(r + 8) * DIM + c) =
                make_float2(acc[mt][nt][2], acc[mt][nt][3]);
        }
}

// ---------------------------------------------------------------------------
// Kernel C: per (batch, half): S = G_half @ X_b^T (tf32 mma, cp.async 3-stage),
// row softmax, colsum(attn) -> w, y = w @ X_b.
// 512 thr = 16 warps (4x4), warp tile 32x64 over S[128x256].
// ---------------------------------------------------------------------------
#define C_STAGE_F (128*20 + 256*20)    // 7680 floats per stage
__global__ void __launch_bounds__(512) attn_kernel(const float* __restrict__ X,
                                                   float* __restrict__ Y2)
{
    extern __shared__ float smem[];
    float* red  = smem + 3 * C_STAGE_F;        // [128][4]
    float* wcol = red + 128 * 4;               // [4][256]
    float* w_s  = wcol + 4 * 256;              // [256]

    int bx   = blockIdx.x;         // 0..1023
    int b    = bx >> 1;
    int half = bx & 1;
    int tid  = threadIdx.x;
    int warp = tid >> 5, lane = tid & 31;
    int wm = warp >> 2, wn = warp & 3;   // 4 x 4
    int gid = lane >> 2, tig = lane & 3;

    const float* Gb = g_G + ((size_t)b * SEQ + half * 128) * DIM;
    const float* Xb = X + (size_t)b * SEQ * DIM;

    int gr = tid >> 2, gk = (tid & 3) * 4;     // G staging: 128 x 16
    int xm = tid >> 1, xk = (tid & 1) * 8;     // X staging: 256 x 16

    float acc[2][8][4];
#pragma unroll
    for (int mt = 0; mt < 2; mt++)
#pragma unroll
        for (int nt = 0; nt < 8; nt++)
#pragma unroll
            for (int r = 0; r < 4; r++) acc[mt][nt][r] = 0.0f;

    auto issue = [&](int s, int kt) {
        float* Gs = smem + s * C_STAGE_F;
        float* Xs = Gs + 128 * 20;
        cp16(&Gs[gr * 20 + gk],     Gb + (size_t)gr * DIM + kt + gk);
        cp16(&Xs[xm * 20 + xk],     Xb + (size_t)xm * DIM + kt + xk);
        cp16(&Xs[xm * 20 + xk + 4], Xb + (size_t)xm * DIM + kt + xk + 4);
    };

    const int NT = DIM / 16;   // 32
    issue(0, 0);  CP_COMMIT();
    issue(1, 16); CP_COMMIT();

    for (int i = 0; i < NT; i++) {
        CP_WAIT1();
        __syncthreads();
        if (i + 2 < NT) issue((i + 2) % 3, (i + 2) * 16);
        CP_COMMIT();

        const float* Gs = smem + (i % 3) * C_STAGE_F;
        const float* Xs = Gs + 128 * 20;
#pragma unroll
        for (int k8 = 0; k8 < 2; k8++) {
            int kb = k8 * 8;
            unsigned af[2][4];
#pragma unroll
            for (int mt = 0; mt < 2; mt++) {
                int row = wm * 32 + mt * 16 + gid;
                af[mt][0] = u32(Gs[row * 20 + kb + tig]);
                af[mt][1] = u32(Gs[(row + 8) * 20 + kb + tig]);
                af[mt][2] = u32(Gs[row * 20 + kb + tig + 4]);
                af[mt][3] = u32(Gs[(row + 8) * 20 + kb + tig + 4]);
            }
            unsigned bf[8][2];
#pragma unroll
            for (int nt = 0; nt < 8; nt++) {
                int col = wn * 64 + nt * 8 + gid;
                bf[nt][0] = u32(Xs[col * 20 + kb + tig]);
                bf[nt][1] = u32(Xs[col * 20 + kb + tig + 4]);
            }
#pragma unroll
            for (int mt = 0; mt < 2; mt++)
#pragma unroll
                for (int nt = 0; nt < 8; nt++)
                    mma_tf32(acc[mt][nt], af[mt][0], af[mt][1], af[mt][2], af[mt][3],
                             bf[nt][0], bf[nt][1]);
        }
    }
    __syncthreads();

    // ---------------- softmax epilogue ----------------
    float rm[2][2];
#pragma unroll
    for (int mt = 0; mt < 2; mt++) {
        float m0 = -1e30f, m1 = -1e30f;
#pragma unroll
        for (int nt = 0; nt < 8; nt++) {
            m0 = fmaxf(m0, fmaxf(acc[mt][nt][0], acc[mt][nt][1]));
            m1 = fmaxf(m1, fmaxf(acc[mt][nt][2], acc[mt][nt][3]));
        }
        m0 = fmaxf(m0, __shfl_xor_sync(0xffffffffu, m0, 1));
        m0 = fmaxf(m0, __shfl_xor_sync(0xffffffffu, m0, 2));
        m1 = fmaxf(m1, __shfl_xor_sync(0xffffffffu, m1, 1));
        m1 = fmaxf(m1, __shfl_xor_sync(0xffffffffu, m1, 2));
        rm[mt][0] = m0; rm[mt][1] = m1;
    }
    if (tig == 0) {
#pragma unroll
        for (int mt = 0; mt < 2; mt++) {
            red[(wm * 32 + mt * 16 + gid) * 4 + wn]     = rm[mt][0];
            red[(wm * 32 + mt * 16 + gid + 8) * 4 + wn] = rm[mt][1];
        }
    }
    __syncthreads();
#pragma unroll
    for (int mt = 0; mt < 2; mt++) {
        int r0 = (wm * 32 + mt * 16 + gid) * 4;
        int r1 = r0 + 32;
        rm[mt][0] = fmaxf(fmaxf(red[r0], red[r0 + 1]), fmaxf(red[r0 + 2], red[r0 + 3]));
        rm[mt][1] = fmaxf(fmaxf(red[r1], red[r1 + 1]), fmaxf(red[r1 + 2], red[r1 + 3]));
    }
    __syncthreads();

    float rs[2][2];
#pragma unroll
    for (int mt = 0; mt < 2; mt++) {
        float s0 = 0.0f, s1 = 0.0f;
#pragma unroll
        for (int nt = 0; nt < 8; nt++) {
            acc[mt][nt][0] = __expf(acc[mt][nt][0] - rm[mt][0]);
            acc[mt][nt][1] = __expf(acc[mt][nt][1] - rm[mt][0]);
            acc[mt][nt][2] = __expf(acc[mt][nt][2] - rm[mt][1]);
            acc[mt][nt][3] = __expf(acc[mt][nt][3] - rm[mt][1]);
            s0 += acc[mt][nt][0] + acc[mt][nt][1];
            s1 += acc[mt][nt][2] + acc[mt][nt][3];
        }
        s0 += __shfl_xor_sync(0xffffffffu, s0, 1);
        s0 += __shfl_xor_sync(0xffffffffu, s0, 2);
        s1 += __shfl_xor_sync(0xffffffffu, s1, 1);
        s1 += __shfl_xor_sync(0xffffffffu, s1, 2);
        rs[mt][0] = s0; rs[mt][1] = s1;
    }
    if (tig == 0) {
#pragma unroll
        for (int mt = 0; mt < 2; mt++) {
            red[(wm * 32 + mt * 16 + gid) * 4 + wn]     = rs[mt][0];
            red[(wm * 32 + mt * 16 + gid + 8) * 4 + wn] = rs[mt][1];
        }
    }
    __syncthreads();
#pragma unroll
    for (int mt = 0; mt < 2; mt++) {
        int r0 = (wm * 32 + mt * 16 + gid) * 4;
        int r1 = r0 + 32;
        rs[mt][0] = 1.0f / (red[r0] + red[r0 + 1] + red[r0 + 2] + red[r0 + 3]);
        rs[mt][1] = 1.0f / (red[r1] + red[r1 + 1] + red[r1 + 2] + red[r1 + 3]);
    }

    float cp[8][2];
#pragma unroll
    for (int nt = 0; nt < 8; nt++) {
        cp[nt][0] = acc[0][nt][0] * rs[0][0] + acc[0][nt][2] * rs[0][1]
                  + acc[1][nt][0] * rs[1][0] + acc[1][nt][2] * rs[1][1];
        cp[nt][1] = acc[0][nt][1] * rs[0][0] + acc[0][nt][3] * rs[0][1]
                  + acc[1][nt][1] * rs[1][0] + acc[1][nt][3] * rs[1][1];
    }
#pragma unroll
    for (int nt = 0; nt < 8; nt++) {
#pragma unroll
        for (int o = 4; o < 32; o <<= 1) {
            cp[nt][0] += __shfl_xor_sync(0xffffffffu, cp[nt][0], o);
            cp[nt][1] += __shfl_xor_sync(0xffffffffu, cp[nt][1], o);
        }
    }
    if (gid == 0) {
#pragma unroll
        for (int nt = 0; nt < 8; nt++) {
            wcol[wm * 256 + wn * 64 + nt * 8 + 2 * tig]     = cp[nt][0];
            wcol[wm * 256 + wn * 64 + nt * 8 + 2 * tig + 1] = cp[nt][1];
        }
    }
    __syncthreads();
    if (tid < 256)
        w_s[tid] = wcol[tid] + wcol[256 + tid] + wcol[512 + tid] + wcol[768 + tid];
    __syncthreads();

    // y_part[d] = sum_m w_s[m] * X_b[m, d]
    {
        int d = tid;
        float y = 0.0f;
#pragma unroll 4
        for (int m = 0; m < SEQ; m++)
            y = fmaf(w_s[m], Xb[(size_t)m * DIM + d], y);
        Y2[(size_t)bx * DIM + d] = y;
    }
}

// ---------------------------------------------------------------------------
// Kernel D: merged = Y @ Wv, Y[b] = Y2[2b] + Y2[2b+1].
// 64x64 tiles, grid 8x8 = 64 CTAs, 256 thr, BK=32, 4x4 microtile.
// ---------------------------------------------------------------------------
__global__ void __launch_bounds__(256) final_gemm_kernel(const float* __restrict__ Wv,
                                                         float* __restrict__ out)
{
    __shared__ float As[32][68];     // [k][batch]
    __shared__ float Bs[32][68];     // [k][col]
    int tid  = threadIdx.x;
    int batch0 = blockIdx.y * 64;
    int col0   = blockIdx.x * 64;

    int ar = tid >> 2, akk = (tid & 3) * 8;   // A staging: 64 batches x 32 k
    int bk = tid >> 3, bn = (tid & 7) * 8;    // B staging: 32 k x 64 cols
    int tr = tid >> 4, tc = tid & 15;

    float acc[4][4];
#pragma unroll
    for (int i = 0; i < 4; i++)
#pragma unroll
        for (int j = 0; j < 4; j++) acc[i][j] = 0.0f;

    for (int kt = 0; kt < DIM; kt += 32) {
        // A: Y[b][k] = Y2[2b][k] + Y2[2b+1][k], stored transposed As[k][b]
        {
            const float* y0 = g_Y2 + (size_t)(2 * (batch0 + ar)) * DIM + kt + akk;
            const float* y1 = y0 + DIM;
            float4 a0 = *(const float4*)y0;
            float4 a1 = *(const float4*)(y0 + 4);
            float4 b0 = *(const float4*)y1;
            float4 b1 = *(const float4*)(y1 + 4);
            As[akk + 0][ar] = a0.x + b0.x;
            As[akk + 1][ar] = a0.y + b0.y;
            As[akk + 2][ar] = a0.z + b0.z;
            As[akk + 3][ar] = a0.w + b0.w;
            As[akk + 4][ar] = a1.x + b1.x;
            As[akk + 5][ar] = a1.y + b1.y;
            As[akk + 6][ar] = a1.z + b1.z;
            As[akk + 7][ar] = a1.w + b1.w;
        }
        // B: Wv rows, natural layout
        {
            const float* wp = Wv + (size_t)(kt + bk) * DIM + col0 + bn;
            *(float4*)(&Bs[bk][bn])     = *(const float4*)wp;
            *(float4*)(&Bs[bk][bn + 4]) = *(const float4*)(wp + 4);
        }
        __syncthreads();
#pragma unroll
        for (int k = 0; k < 32; k++) {
            float4 ra = *(const float4*)(&As[k][tr * 4]);
            float4 rb = *(const float4*)(&Bs[k][tc * 4]);
            float a[4] = {ra.x, ra.y, ra.z, ra.w};
            float b[4] = {rb.x, rb.y, rb.z, rb.w};
#pragma unroll
            for (int i = 0; i < 4; i++)
#pragma unroll
                for (int j = 0; j < 4; j++)
                    acc[i][j] += a[i] * b[j];
        }
        __syncthreads();
    }
#pragma unroll
    for (int i = 0; i < 4; i++) {
        float* op = out + (size_t)(batch0 + tr * 4 + i) * DIM + col0 + tc * 4;
        *(float4*)op = make_float4(acc[i][0], acc[i][1], acc[i][2], acc[i][3]);
    }
}

// ---------------------------------------------------------------------------
// Launch
// ---------------------------------------------------------------------------
extern "C" void kernel_launch(void* const* d_in, const int* in_sizes, int n_in,
                              void* d_out, int out_size)
{
    const float* X  = (const float*)d_in[0];   // [512,256,512]
    const float* Wq = (const float*)d_in[1];   // [512,512]
    const float* Wk = (const float*)d_in[2];
    const float* Wv = (const float*)d_in[3];
    float* out = (float*)d_out;                // [512,512]

    float* G;
    float* Y2;
    cudaGetSymbolAddress((void**)&G,  g_G);
    cudaGetSymbolAddress((void**)&Y2, g_Y2);

    const int smemB = 3 * B_STAGE_F * sizeof(float);                  // ~55.5 KB
    const int smemC = 3 * C_STAGE_F * sizeof(float) + (512 + 1024 + 256) * sizeof(float); // ~97 KB
    cudaFuncSetAttribute(gemm_G_kernel, cudaFuncAttributeMaxDynamicSharedMemorySize, smemB);
    cudaFuncSetAttribute(attn_kernel,   cudaFuncAttributeMaxDynamicSharedMemorySize, smemC);

    // A: M = norm * Wq @ Wk^T
    wqwk_kernel<<<dim3(8, 8), 256>>>(Wq, Wk);
    // B: G = Xflat @ M  (tf32 tensor cores, cp.async pipeline)
    gemm_G_kernel<<<dim3(4, 1024), 256, smemB>>>(X, G);
    // C: fused scores/softmax/colsum/y per (batch, half)
    attn_kernel<<<1024, 512, smemC>>>(X, Y2);
    // D: merged = (Y2[2b]+Y2[2b+1]) @ Wv
    final_gemm_kernel<<<dim3(8, 8), 256>>>(Wv, out);
}

// round 12
// speedup vs baseline: 1.6775x; 1.0631x over previous
#include <cuda_runtime.h>
#include <cuda_bf16.h>
#include <cuda_fp16.h>
#include <math.h>

// Problem shape
#define BATCH 512
#define SEQ   256
#define DIM   512
#define NORM  0.044194173824159216f   // 1/sqrt(512)

// Scratch (static __device__ — no dynamic allocation allowed)
__device__ __half2 g_Mh2[(DIM / 2) * DIM];               // M packed pairs along k: [k2][n]
__device__ __half  g_Xh[(size_t)BATCH * SEQ * DIM];      // X as half, [m][k]
__device__ __half2 g_XhT2[(size_t)BATCH * (DIM / 2) * SEQ]; // per-batch [k2][m], pair-packed k
__device__ __half  g_Gh[(size_t)BATCH * SEQ * DIM];      // G as half, [row][n]
__device__ float   g_Y2[(size_t)BATCH * 2 * DIM];        // per-half y contributions

extern __shared__ float dynsmem[];

// ---------------------------------------------------------------------------
// helpers
// ---------------------------------------------------------------------------
__device__ __forceinline__ void cp16g(unsigned sa, const void* g) {
    asm volatile("cp.async.cg.shared.global [%0], [%1], 16;" :: "r"(sa), "l"(g));
}
__device__ __forceinline__ void cp8g(unsigned sa, const void* g) {
    asm volatile("cp.async.ca.shared.global [%0], [%1], 8;" :: "r"(sa), "l"(g));
}
#define CP_COMMIT() asm volatile("cp.async.commit_group;")
#define CP_WAIT1()  asm volatile("cp.async.wait_group 1;")
#define CP_WAIT0()  asm volatile("cp.async.wait_group 0;")

__device__ __forceinline__ void mma_f16(float c[4],
                                        unsigned a0, unsigned a1, unsigned a2, unsigned a3,
                                        unsigned b0, unsigned b1) {
    asm("mma.sync.aligned.m16n8k16.row.col.f32.f16.f16.f32 "
        "{%0,%1,%2,%3}, {%4,%5,%6,%7}, {%8,%9}, {%0,%1,%2,%3};"
        : "+f"(c[0]), "+f"(c[1]), "+f"(c[2]), "+f"(c[3])
        : "r"(a0), "r"(a1), "r"(a2), "r"(a3), "r"(b0), "r"(b1));
}
__device__ __forceinline__ unsigned sm_u32(const void* p) {
    return (unsigned)__cvta_generic_to_shared(p);
}

// ---------------------------------------------------------------------------
// Kernel X2H: Xh[m][k] (half) and XhT2[b][k2][m] (half2, k-pair packed)
// grid (8 ktile, 4 mtile, 512 batch), 256 thr, 64x64 tile via smem
// ---------------------------------------------------------------------------
__global__ void __launch_bounds__(256) x2h_kernel(const float* __restrict__ X)
{
    __shared__ float s[64][65];
    int tid = threadIdx.x;
    int ktile = blockIdx.x, mtile = blockIdx.y, b = blockIdx.z;

    int r = tid >> 2, c4 = (tid & 3) * 16;
    const float* src = X + ((size_t)b * SEQ + mtile * 64 + r) * DIM + ktile * 64 + c4;
    __half* xh = g_Xh + ((size_t)b * SEQ + mtile * 64 + r) * DIM + ktile * 64 + c4;
#pragma unroll
    for (int i = 0; i < 4; i++) {
        float4 v = *(const float4*)(src + i * 4);
        s[r][c4 + i * 4 + 0] = v.x;
        s[r][c4 + i * 4 + 1] = v.y;
        s[r][c4 + i * 4 + 2] = v.z;
        s[r][c4 + i * 4 + 3] = v.w;
        *(__half2*)(xh + i * 4)     = __floats2half2_rn(v.x, v.y);
        *(__half2*)(xh + i * 4 + 2) = __floats2half2_rn(v.z, v.w);
    }
    __syncthreads();

    // transposed pair-packed write: element (k2, m) = (X[m][2k2], X[m][2k2+1])
    int k2l = tid >> 3;          // 0..31
    int ml  = (tid & 7) * 8;     // 0..56
    __half2* dst = g_XhT2 + ((size_t)b * (DIM / 2) + ktile * 32 + k2l) * SEQ
                 + mtile * 64 + ml;
#pragma unroll
    for (int mm = 0; mm < 8; mm++)
        dst[mm] = __floats2half2_rn(s[ml + mm][2 * k2l], s[ml + mm][2 * k2l + 1]);
}

// ---------------------------------------------------------------------------
// Kernel A: Mh2 = pack(norm * Wq @ Wk^T).  64x64 tiles, grid 8x8, 256 thr.
// Mh2[k2][n] = (M[2k2][n], M[2k2+1][n]),  M rows = input dim k.
// ---------------------------------------------------------------------------
__global__ void __launch_bounds__(256) wqwk_kernel(const float* __restrict__ Wq,
                                                   const float* __restrict__ Wk)
{
    __shared__ float As[32][68];   // [e][row]
    __shared__ float Bs[32][68];   // [e][col]
    int tid = threadIdx.x;
    int row0 = blockIdx.y * 64;
    int col0 = blockIdx.x * 64;

    int sr = tid >> 2, se = (tid & 3) * 8;
    int tr = tid >> 4, tc = tid & 15;

    float acc[4][4];
#pragma unroll
    for (int i = 0; i < 4; i++)
#pragma unroll
        for (int j = 0; j < 4; j++) acc[i][j] = 0.0f;

    for (int kt = 0; kt < DIM; kt += 32) {
        float4 q0 = *(const float4*)(Wq + (size_t)(row0 + sr) * DIM + kt + se);
        float4 q1 = *(const float4*)(Wq + (size_t)(row0 + sr) * DIM + kt + se + 4);
        float4 k0 = *(const float4*)(Wk + (size_t)(col0 + sr) * DIM + kt + se);
        float4 k1 = *(const float4*)(Wk + (size_t)(col0 + sr) * DIM + kt + se + 4);
        As[se + 0][sr] = q0.x; As[se + 1][sr] = q0.y;
        As[se + 2][sr] = q0.z; As[se + 3][sr] = q0.w;
        As[se + 4][sr] = q1.x; As[se + 5][sr] = q1.y;
        As[se + 6][sr] = q1.z; As[se + 7][sr] = q1.w;
        Bs[se + 0][sr] = k0.x; Bs[se + 1][sr] = k0.y;
        Bs[se + 2][sr] = k0.z; Bs[se + 3][sr] = k0.w;
        Bs[se + 4][sr] = k1.x; Bs[se + 5][sr] = k1.y;
        Bs[se + 6][sr] = k1.z; Bs[se + 7][sr] = k1.w;
        __syncthreads();
#pragma unroll
        for (int k = 0; k < 32; k++) {
            float4 ra = *(const float4*)(&As[k][tr * 4]);
            float4 rb = *(const float4*)(&Bs[k][tc * 4]);
            float a[4] = {ra.x, ra.y, ra.z, ra.w};
            float b[4] = {rb.x, rb.y, rb.z, rb.w};
#pragma unroll
            for (int i = 0; i < 4; i++)
#pragma unroll
                for (int j = 0; j < 4; j++)
                    acc[i][j] += a[i] * b[j];
        }
        __syncthreads();
    }
    // pack row pairs (tr*4+0, +1) and (+2, +3)
    int k2b = (row0 >> 1) + tr * 2;
#pragma unroll
    for (int j = 0; j < 4; j++) {
        int n = col0 + tc * 4 + j;
        g_Mh2[(size_t)k2b * DIM + n] =
            __floats2half2_rn(acc[0][j] * NORM, acc[1][j] * NORM);
        g_Mh2[(size_t)(k2b + 1) * DIM + n] =
            __floats2half2_rn(acc[2][j] * NORM, acc[3][j] * NORM);
    }
}

// ---------------------------------------------------------------------------
// Kernel B: G = X @ M via fp16 mma.sync (k16), cp.async 3-stage pipeline.
// CTA 128x128, BK=16, 256 thr = 8 warps (2x4), warp tile 64x32.
// smem b32 units: As2[128][12] (pairs along k), Bs2[8][136].
// ---------------------------------------------------------------------------
#define B_STAGE_U (128*12 + 8*136)     // 2624 b32 per stage
__global__ void __launch_bounds__(256) gemm_G_kernel()
{
    unsigned* smem = (unsigned*)dynsmem;
    int tid  = threadIdx.x;
    int cCol = blockIdx.x;            // 0..3
    int cRow = blockIdx.y;            // 0..1023
    int warp = tid >> 5, lane = tid & 31;
    int wm = warp >> 2, wn = warp & 3;
    int gid = lane >> 2, tig = lane & 3;

    const __half*  Ab = g_Xh + (size_t)cRow * 128 * DIM;
    const __half2* Mb = g_Mh2;        // [k2][n]
    __half*        Gb = g_Gh + (size_t)cRow * 128 * DIM + cCol * 128;

    int ar = tid >> 1, ak2 = (tid & 1) * 4;    // A: 128 rows x 8 half2
    int bk2 = tid >> 5, bn = (tid & 31) * 4;   // B: 8 k2-rows x 128 n

    float acc[4][4][4];
#pragma unroll
    for (int mt = 0; mt < 4; mt++)
#pragma unroll
        for (int nt = 0; nt < 4; nt++)
#pragma unroll
            for (int r = 0; r < 4; r++) acc[mt][nt][r] = 0.0f;

    unsigned smem_b = sm_u32(smem);
    auto issue = [&](int s, int kt) {
        unsigned abase = smem_b + s * B_STAGE_U * 4;
        unsigned bbase = abase + 128 * 12 * 4;
        cp16g(abase + (ar * 12 + ak2) * 4, Ab + (size_t)ar * DIM + kt + ak2 * 2);
        cp16g(bbase + (bk2 * 136 + bn) * 4,
              Mb + (size_t)(kt / 2 + bk2) * DIM + cCol * 128 + bn);
        CP_COMMIT();
    };

    const int NT = DIM / 16;   // 32
    issue(0, 0);
    issue(1, 16);

    for (int i = 0; i < NT; i++) {
        if (i + 1 < NT) CP_WAIT1(); else CP_WAIT0();
        __syncthreads();
        if (i + 2 < NT) issue((i + 2) % 3, (i + 2) * 16);

        const unsigned* As2 = smem + (i % 3) * B_STAGE_U;
        const unsigned* Bs2 = As2 + 128 * 12;
        unsigned af[4][4];
#pragma unroll
        for (int mt = 0; mt < 4; mt++) {
            int row = wm * 64 + mt * 16 + gid;
            af[mt][0] = As2[row * 12 + tig];
            af[mt][1] = As2[(row + 8) * 12 + tig];
            af[mt][2] = As2[row * 12 + tig + 4];
            af[mt][3] = As2[(row + 8) * 12 + tig + 4];
        }
        unsigned bf[4][2];
#pragma unroll
        for (int nt = 0; nt < 4; nt++) {
            int col = wn * 32 + nt * 8 + gid;
            bf[nt][0] = Bs2[tig * 136 + col];
            bf[nt][1] = Bs2[(tig + 4) * 136 + col];
        }
#pragma unroll
        for (int mt = 0; mt < 4; mt++)
#pragma unroll
            for (int nt = 0; nt < 4; nt++)
                mma_f16(acc[mt][nt], af[mt][0], af[mt][1], af[mt][2], af[mt][3],
                        bf[nt][0], bf[nt][1]);
        __syncthreads();
    }

    // epilogue: store G as half
#pragma unroll
    for (int mt = 0; mt < 4; mt++)
#pragma unroll
        for (int nt = 0; nt < 4; nt++) {
            int r = wm * 64 + mt * 16 + gid;
            int c = wn * 32 + nt * 8 + 2 * tig;
            *(__half2*)(Gb + (size_t)r * DIM + c) =
                __floats2half2_rn(acc[mt][nt][0], acc[mt][nt][1]);
            *(__half2*)(Gb + (size_t)(r + 8) * DIM + c) =
                __floats2half2_rn(acc[mt][nt][2], acc[mt][nt][3]);
        }
}

// ---------------------------------------------------------------------------
// Kernel C: per (batch, half): S = G_half @ X_b^T (fp16 mma, 3-stage),
// row softmax, colsum(attn) -> w, y = w @ X_b.
// 512 thr = 16 warps (4x4), warp tile 32x64 over S[128x256].
// smem b32: Gs2[128][12], Xs2[8][264].
// ---------------------------------------------------------------------------
#define C_STAGE_U (128*12 + 8*264)     // 3648 b32 per stage
__global__ void __launch_bounds__(512) attn_kernel(float* __restrict__ Y2)
{
    unsigned* usmem = (unsigned*)dynsmem;
    float* red  = dynsmem + 3 * C_STAGE_U;     // [128][4]
    float* wcol = red + 128 * 4;               // [4][256]
    float* w_s  = wcol + 4 * 256;              // [256]

    int bx   = blockIdx.x;         // 0..1023
    int b    = bx >> 1;
    int half = bx & 1;
    int tid  = threadIdx.x;
    int warp = tid >> 5, lane = tid & 31;
    int wm = warp >> 2, wn = warp & 3;   // 4 x 4
    int gid = lane >> 2, tig = lane & 3;

    const __half*  Gbh = g_Gh + ((size_t)b * SEQ + half * 128) * DIM;
    const __half2* Xt  = g_XhT2 + (size_t)b * (DIM / 2) * SEQ;
    const __half*  Xbh = g_Xh + (size_t)b * SEQ * DIM;

    int gr = tid >> 2, gk2 = (tid & 3) * 2;    // G: 128 rows x 8 half2, cp8 each
    int xk2 = tid >> 6, xm = (tid & 63) * 4;   // X: 8 k2-rows x 256 m, cp16 each

    float acc[2][8][4];
#pragma unroll
    for (int mt = 0; mt < 2; mt++)
#pragma unroll
        for (int nt = 0; nt < 8; nt++)
#pragma unroll
            for (int r = 0; r < 4; r++) acc[mt][nt][r] = 0.0f;

    unsigned smem_b = sm_u32(usmem);
    auto issue = [&](int s, int kt) {
        unsigned gbase = smem_b + s * C_STAGE_U * 4;
        unsigned xbase = gbase + 128 * 12 * 4;
        cp8g(gbase + (gr * 12 + gk2) * 4, Gbh + (size_t)gr * DIM + kt + gk2 * 2);
        cp16g(xbase + (xk2 * 264 + xm) * 4,
              Xt + (size_t)(kt / 2 + xk2) * SEQ + xm);
        CP_COMMIT();
    };

    const int NT = DIM / 16;   // 32
    issue(0, 0);
    issue(1, 16);

    for (int i = 0; i < NT; i++) {
        if (i + 1 < NT) CP_WAIT1(); else CP_WAIT0();
        __syncthreads();
        if (i + 2 < NT) issue((i + 2) % 3, (i + 2) * 16);

        const unsigned* Gs2 = usmem + (i % 3) * C_STAGE_U;
        const unsigned* Xs2 = Gs2 + 128 * 12;
        unsigned af[2][4];
#pragma unroll
        for (int mt = 0; mt < 2; mt++) {
            int row = wm * 32 + mt * 16 + gid;
            af[mt][0] = Gs2[row * 12 + tig];
            af[mt][1] = Gs2[(row + 8) * 12 + tig];
            af[mt][2] = Gs2[row * 12 + tig + 4];
            af[mt][3] = Gs2[(row + 8) * 12 + tig + 4];
        }
        unsigned bf[8][2];
#pragma unroll
        for (int nt = 0; nt < 8; nt++) {
            int col = wn * 64 + nt * 8 + gid;
            bf[nt][0] = Xs2[tig * 264 + col];
            bf[nt][1] = Xs2[(tig + 4) * 264 + col];
        }
#pragma unroll
        for (int mt = 0; mt < 2; mt++)
#pragma unroll
            for (int nt = 0; nt < 8; nt++)
                mma_f16(acc[mt][nt], af[mt][0], af[mt][1], af[mt][2], af[mt][3],
                        bf[nt][0], bf[nt][1]);
        __syncthreads();
    }

    // ---------------- softmax epilogue ----------------
    float rm[2][2];
#pragma unroll
    for (int mt = 0; mt < 2; mt++) {
        float m0 = -1e30f, m1 = -1e30f;
#pragma unroll
        for (int nt = 0; nt < 8; nt++) {
            m0 = fmaxf(m0, fmaxf(acc[mt][nt][0], acc[mt][nt][1]));
            m1 = fmaxf(m1, fmaxf(acc[mt][nt][2], acc[mt][nt][3]));
        }
        m0 = fmaxf(m0, __shfl_xor_sync(0xffffffffu, m0, 1));
        m0 = fmaxf(m0, __shfl_xor_sync(0xffffffffu, m0, 2));
        m1 = fmaxf(m1, __shfl_xor_sync(0xffffffffu, m1, 1));
        m1 = fmaxf(m1, __shfl_xor_sync(0xffffffffu, m1, 2));
        rm[mt][0] = m0; rm[mt][1] = m1;
    }
    if (tig == 0) {
#pragma unroll
        for (int mt = 0; mt < 2; mt++) {
            red[(wm * 32 + mt * 16 + gid) * 4 + wn]     = rm[mt][0];
            red[(wm * 32 + mt * 16 + gid + 8) * 4 + wn] = rm[mt][1];
        }
    }
    __syncthreads();
#pragma unroll
    for (int mt = 0; mt < 2; mt++) {
        int r0 = (wm * 32 + mt * 16 + gid) * 4;
        int r1 = r0 + 32;
        rm[mt][0] = fmaxf(fmaxf(red[r0], red[r0 + 1]), fmaxf(red[r0 + 2], red[r0 + 3]));
        rm[mt][1] = fmaxf(fmaxf(red[r1], red[r1 + 1]), fmaxf(red[r1 + 2], red[r1 + 3]));
    }
    __syncthreads();

    float rs[2][2];
#pragma unroll
    for (int mt = 0; mt < 2; mt++) {
        float s0 = 0.0f, s1 = 0.0f;
#pragma unroll
        for (int nt = 0; nt < 8; nt++) {
            acc[mt][nt][0] = __expf(acc[mt][nt][0] - rm[mt][0]);
            acc[mt][nt][1] = __expf(acc[mt][nt][1] - rm[mt][0]);
            acc[mt][nt][2] = __expf(acc[mt][nt][2] - rm[mt][1]);
            acc[mt][nt][3] = __expf(acc[mt][nt][3] - rm[mt][1]);
            s0 += acc[mt][nt][0] + acc[mt][nt][1];
            s1 += acc[mt][nt][2] + acc[mt][nt][3];
        }
        s0 += __shfl_xor_sync(0xffffffffu, s0, 1);
        s0 += __shfl_xor_sync(0xffffffffu, s0, 2);
        s1 += __shfl_xor_sync(0xffffffffu, s1, 1);
        s1 += __shfl_xor_sync(0xffffffffu, s1, 2);
        rs[mt][0] = s0; rs[mt][1] = s1;
    }
    if (tig == 0) {
#pragma unroll
        for (int mt = 0; mt < 2; mt++) {
            red[(wm * 32 + mt * 16 + gid) * 4 + wn]     = rs[mt][0];
            red[(wm * 32 + mt * 16 + gid + 8) * 4 + wn] = rs[mt][1];
        }
    }
    __syncthreads();
#pragma unroll
    for (int mt = 0; mt < 2; mt++) {
        int r0 = (wm * 32 + mt * 16 + gid) * 4;
        int r1 = r0 + 32;
        rs[mt][0] = 1.0f / (red[r0] + red[r0 + 1] + red[r0 + 2] + red[r0 + 3]);
        rs[mt][1] = 1.0f / (red[r1] + red[r1 + 1] + red[r1 + 2] + red[r1 + 3]);
    }

    float cp[8][2];
#pragma unroll
    for (int nt = 0; nt < 8; nt++) {
        cp[nt][0] = acc[0][nt][0] * rs[0][0] + acc[0][nt][2] * rs[0][1]
                  + acc[1][nt][0] * rs[1][0] + acc[1][nt][2] * rs[1][1];
        cp[nt][1] = acc[0][nt][1] * rs[0][0] + acc[0][nt][3] * rs[0][1]
                  + acc[1][nt][1] * rs[1][0] + acc[1][nt][3] * rs[1][1];
    }
#pragma unroll
    for (int nt = 0; nt < 8; nt++) {
#pragma unroll
        for (int o = 4; o < 32; o <<= 1) {
            cp[nt][0] += __shfl_xor_sync(0xffffffffu, cp[nt][0], o);
            cp[nt][1] += __shfl_xor_sync(0xffffffffu, cp[nt][1], o);
        }
    }
    if (gid == 0) {
#pragma unroll
        for (int nt = 0; nt < 8; nt++) {
            wcol[wm * 256 + wn * 64 + nt * 8 + 2 * tig]     = cp[nt][0];
            wcol[wm * 256 + wn * 64 + nt * 8 + 2 * tig + 1] = cp[nt][1];
        }
    }
    __syncthreads();
    if (tid < 256)
        w_s[tid] = wcol[tid] + wcol[256 + tid] + wcol[512 + tid] + wcol[768 + tid];
    __syncthreads();

    // y_part[d] = sum_m w_s[m] * X_b[m, d]   (read half X)
    {
        int d = tid;
        float y = 0.0f;
#pragma unroll 4
        for (int m = 0; m < SEQ; m++)
            y = fmaf(w_s[m], __half2float(Xbh[(size_t)m * DIM + d]), y);
        Y2[(size_t)bx * DIM + d] = y;
    }
}

// ---------------------------------------------------------------------------
// Kernel D: merged = Y @ Wv, Y[b] = Y2[2b] + Y2[2b+1].  (unchanged, fp32)
// ---------------------------------------------------------------------------
__global__ void __launch_bounds__(256) final_gemm_kernel(const float* __restrict__ Wv,
                                                         float* __restrict__ out)
{
    __shared__ float As[32][68];
    __shared__ float Bs[32][68];
    int tid  = threadIdx.x;
    int batch0 = blockIdx.y * 64;
    int col0   = blockIdx.x * 64;

    int ar = tid >> 2, akk = (tid & 3) * 8;
    int bk = tid >> 3, bn = (tid & 7) * 8;
    int tr = tid >> 4, tc = tid & 15;

    float acc[4][4];
#pragma unroll
    for (int i = 0; i < 4; i++)
#pragma unroll
        for (int j = 0; j < 4; j++) acc[i][j] = 0.0f;

    for (int kt = 0; kt < DIM; kt += 32) {
        {
            const float* y0 = g_Y2 + (size_t)(2 * (batch0 + ar)) * DIM + kt + akk;
            const float* y1 = y0 + DIM;
            float4 a0 = *(const float4*)y0;
            float4 a1 = *(const float4*)(y0 + 4);
            float4 b0 = *(const float4*)y1;
            float4 b1 = *(const float4*)(y1 + 4);
            As[akk + 0][ar] = a0.x + b0.x;
            As[akk + 1][ar] = a0.y + b0.y;
            As[akk + 2][ar] = a0.z + b0.z;
            As[akk + 3][ar] = a0.w + b0.w;
            As[akk + 4][ar] = a1.x + b1.x;
            As[akk + 5][ar] = a1.y + b1.y;
            As[akk + 6][ar] = a1.z + b1.z;
            As[akk + 7][ar] = a1.w + b1.w;
        }
        {
            const float* wp = Wv + (size_t)(kt + bk) * DIM + col0 + bn;
            *(float4*)(&Bs[bk][bn])     = *(const float4*)wp;
            *(float4*)(&Bs[bk][bn + 4]) = *(const float4*)(wp + 4);
        }
        __syncthreads();
#pragma unroll
        for (int k = 0; k < 32; k++) {
            float4 ra = *(const float4*)(&As[k][tr * 4]);
            float4 rb = *(const float4*)(&Bs[k][tc * 4]);
            float a[4] = {ra.x, ra.y, ra.z, ra.w};
            float b[4] = {rb.x, rb.y, rb.z, rb.w};
#pragma unroll
            for (int i = 0; i < 4; i++)
#pragma unroll
                for (int j = 0; j < 4; j++)
                    acc[i][j] += a[i] * b[j];
        }
        __syncthreads();
    }
#pragma unroll
    for (int i = 0; i < 4; i++) {
        float* op = out + (size_t)(batch0 + tr * 4 + i) * DIM + col0 + tc * 4;
        *(float4*)op = make_float4(acc[i][0], acc[i][1], acc[i][2], acc[i][3]);
    }
}

// ---------------------------------------------------------------------------
// Launch
// ---------------------------------------------------------------------------
extern "C" void kernel_launch(void* const* d_in, const int* in_sizes, int n_in,
                              void* d_out, int out_size)
{
    const float* X  = (const float*)d_in[0];   // [512,256,512]
    const float* Wq = (const float*)d_in[1];   // [512,512]
    const float* Wk = (const float*)d_in[2];
    const float* Wv = (const float*)d_in[3];
    float* out = (float*)d_out;                // [512,512]

    float* Y2;
    cudaGetSymbolAddress((void**)&Y2, g_Y2);

    const int smemB = B_STAGE_U * 3 * 4;                        // ~31.5 KB
    const int smemC = C_STAGE_U * 3 * 4 + 1792 * 4;             // ~50.9 KB
    cudaFuncSetAttribute(gemm_G_kernel, cudaFuncAttributeMaxDynamicSharedMemorySize, smemB);
    cudaFuncSetAttribute(attn_kernel,   cudaFuncAttributeMaxDynamicSharedMemorySize, smemC);

    // X -> half (plain + transposed pair-packed)
    x2h_kernel<<<dim3(8, 4, 512), 256>>>(X);
    // A: Mh2 = pack(norm * Wq @ Wk^T)
    wqwk_kernel<<<dim3(8, 8), 256>>>(Wq, Wk);
    // B: G = X @ M  (fp16 mma.sync)
    gemm_G_kernel<<<dim3(4, 1024), 256, smemB>>>();
    // C: fused scores/softmax/colsum/y per (batch, half)
    attn_kernel<<<1024, 512, smemC>>>(Y2);
    // D: merged = (Y2[2b]+Y2[2b+1]) @ Wv
    final_gemm_kernel<<<dim3(8, 8), 256>>>(Wv, out);
}

// round 13
// speedup vs baseline: 2.3838x; 1.4211x over previous
#include <cuda_runtime.h>
#include <cuda_bf16.h>
#include <cuda_fp16.h>
#include <math.h>

// Problem shape
#define BATCH 512
#define SEQ   256
#define DIM   512
#define NORM  0.044194173824159216f   // 1/sqrt(512)

// Quad-packed fp16 operand layout:
//   Q[row][m], row = kgroup*4 + j, packs halves (v[m][16g+2j], [+1], [+8], [+9])
//   -> b-fragment = 1 LDS.64, a-fragment = 2 LDS.64 (row, row+8)
__device__ uint2 g_MQ[128 * DIM];                     // M quads: [kg*4+j][n]
__device__ uint2 g_XQ[(size_t)BATCH * 128 * SEQ];     // X quads: [b*128 + kg*4+j][m]
__device__ uint2 g_GQ[(size_t)BATCH * 128 * SEQ];     // G quads: [b*128 + ng*4+j][m]
__device__ float g_Y2[(size_t)BATCH * 2 * DIM];       // per-half y contributions

extern __shared__ float dynsmem[];

// ---------------------------------------------------------------------------
// helpers
// ---------------------------------------------------------------------------
__device__ __forceinline__ void cp16g(unsigned sa, const void* g) {
    asm volatile("cp.async.cg.shared.global [%0], [%1], 16;" :: "r"(sa), "l"(g));
}
#define CP_COMMIT() asm volatile("cp.async.commit_group;")
#define CP_WAIT1()  asm volatile("cp.async.wait_group 1;")
#define CP_WAIT0()  asm volatile("cp.async.wait_group 0;")

__device__ __forceinline__ void mma_f16(float c[4],
                                        unsigned a0, unsigned a1, unsigned a2, unsigned a3,
                                        unsigned b0, unsigned b1) {
    asm("mma.sync.aligned.m16n8k16.row.col.f32.f16.f16.f32 "
        "{%0,%1,%2,%3}, {%4,%5,%6,%7}, {%8,%9}, {%0,%1,%2,%3};"
        : "+f"(c[0]), "+f"(c[1]), "+f"(c[2]), "+f"(c[3])
        : "r"(a0), "r"(a1), "r"(a2), "r"(a3), "r"(b0), "r"(b1));
}
__device__ __forceinline__ unsigned sm_u32(const void* p) {
    return (unsigned)__cvta_generic_to_shared(p);
}
__device__ __forceinline__ uint2 packq(float a, float b, float c, float d) {
    __half2 lo = __floats2half2_rn(a, b);
    __half2 hi = __floats2half2_rn(c, d);
    uint2 r;
    r.x = *(unsigned*)&lo;
    r.y = *(unsigned*)&hi;
    return r;
}

// ---------------------------------------------------------------------------
// Kernel X2H: X (fp32) -> g_XQ quad-packed fp16.
// grid (8 ktile, 4 mtile, 512 batch), 256 thr, 64x64 tile via smem.
// ---------------------------------------------------------------------------
__global__ void __launch_bounds__(256) x2h_kernel(const float* __restrict__ X)
{
    __shared__ float s[64][65];
    int tid = threadIdx.x;
    int ktile = blockIdx.x, mtile = blockIdx.y, b = blockIdx.z;

    int r = tid >> 2, c4 = (tid & 3) * 16;
    const float* src = X + ((size_t)b * SEQ + mtile * 64 + r) * DIM + ktile * 64 + c4;
#pragma unroll
    for (int i = 0; i < 4; i++) {
        float4 v = *(const float4*)(src + i * 4);
        s[r][c4 + i * 4 + 0] = v.x;
        s[r][c4 + i * 4 + 1] = v.y;
        s[r][c4 + i * 4 + 2] = v.z;
        s[r][c4 + i * 4 + 3] = v.w;
    }
    __syncthreads();

    int q = tid >> 4, g = q >> 2, j = q & 3;
    int ml = (tid & 15) * 4;
    int kb = g * 16 + 2 * j;
    size_t row = (size_t)b * 128 + (ktile * 4 + g) * 4 + j;
    uint2* dst = g_XQ + row * SEQ + mtile * 64 + ml;
#pragma unroll
    for (int i = 0; i < 4; i++)
        dst[i] = packq(s[ml + i][kb], s[ml + i][kb + 1],
                       s[ml + i][kb + 8], s[ml + i][kb + 9]);
}

// ---------------------------------------------------------------------------
// Kernel A: M = norm * Wq @ Wk^T -> g_MQ quad-packed.  64x64 tiles, grid 8x8.
// ---------------------------------------------------------------------------
__global__ void __launch_bounds__(256) wqwk_kernel(const float* __restrict__ Wq,
                                                   const float* __restrict__ Wk)
{
    __shared__ float As[32][68];   // [e][row]
    __shared__ float Bs[32][68];   // [e][col]
    __shared__ float Ms[64][65];   // staging for quad pack
    int tid = threadIdx.x;
    int row0 = blockIdx.y * 64;    // k-dim of M
    int col0 = blockIdx.x * 64;    // n-dim of M

    int sr = tid >> 2, se = (tid & 3) * 8;
    int tr = tid >> 4, tc = tid & 15;

    float acc[4][4];
#pragma unroll
    for (int i = 0; i < 4; i++)
#pragma unroll
        for (int jj = 0; jj < 4; jj++) acc[i][jj] = 0.0f;

    for (int kt = 0; kt < DIM; kt += 32) {
        float4 q0 = *(const float4*)(Wq + (size_t)(row0 + sr) * DIM + kt + se);
        float4 q1 = *(const float4*)(Wq + (size_t)(row0 + sr) * DIM + kt + se + 4);
        float4 k0 = *(const float4*)(Wk + (size_t)(col0 + sr) * DIM + kt + se);
        float4 k1 = *(const float4*)(Wk + (size_t)(col0 + sr) * DIM + kt + se + 4);
        As[se + 0][sr] = q0.x; As[se + 1][sr] = q0.y;
        As[se + 2][sr] = q0.z; As[se + 3][sr] = q0.w;
        As[se + 4][sr] = q1.x; As[se + 5][sr] = q1.y;
        As[se + 6][sr] = q1.z; As[se + 7][sr] = q1.w;
        Bs[se + 0][sr] = k0.x; Bs[se + 1][sr] = k0.y;
        Bs[se + 2][sr] = k0.z; Bs[se + 3][sr] = k0.w;
        Bs[se + 4][sr] = k1.x; Bs[se + 5][sr] = k1.y;
        Bs[se + 6][sr] = k1.z; Bs[se + 7][sr] = k1.w;
        __syncthreads();
#pragma unroll
        for (int k = 0; k < 32; k++) {
            float4 ra = *(const float4*)(&As[k][tr * 4]);
            float4 rb = *(const float4*)(&Bs[k][tc * 4]);
            float a[4] = {ra.x, ra.y, ra.z, ra.w};
            float b[4] = {rb.x, rb.y, rb.z, rb.w};
#pragma unroll
            for (int i = 0; i < 4; i++)
#pragma unroll
                for (int jj = 0; jj < 4; jj++)
                    acc[i][jj] += a[i] * b[jj];
        }
        __syncthreads();
    }
    // stage into Ms [local k][local n]
#pragma unroll
    for (int i = 0; i < 4; i++)
#pragma unroll
        for (int jj = 0; jj < 4; jj++)
            Ms[tr * 4 + i][tc * 4 + jj] = acc[i][jj] * NORM;
    __syncthreads();

    // quad pack -> g_MQ
    int q = tid >> 4, g = q >> 2, j = q & 3;
    int nl = (tid & 15) * 4;
    int kb = g * 16 + 2 * j;
    size_t rowI = (size_t)((row0 >> 4) + g) * 4 + j;
#pragma unroll
    for (int i = 0; i < 4; i++) {
        int n = nl + i;
        g_MQ[rowI * DIM + col0 + n] = packq(Ms[kb][n], Ms[kb + 1][n],
                                            Ms[kb + 8][n], Ms[kb + 9][n]);
    }
}

// ---------------------------------------------------------------------------
// Kernel B: G = X @ M via fp16 mma (k16), all operands quad-packed.
// CTA 128x128, BK=32, 256 thr = 8 warps (2x4), warp tile 64x32. 3-stage cp.async.
// ---------------------------------------------------------------------------
#define B_ST 2112   // b64 per stage: A 8*132 + M 8*132
__global__ void __launch_bounds__(256) gemm_G_kernel()
{
    uint2* sm = (uint2*)dynsmem;
    int tid = threadIdx.x;
    int cCol = blockIdx.x;            // 0..3
    int cRow = blockIdx.y;            // 0..1023
    int warp = tid >> 5, lane = tid & 31;
    int wm = warp >> 2, wn = warp & 3;
    int gid = lane >> 2, tig = lane & 3;
    int bb = cRow >> 1, m0 = (cRow & 1) * 128;

    float acc[4][4][4];
#pragma unroll
    for (int mt = 0; mt < 4; mt++)
#pragma unroll
        for (int nt = 0; nt < 4; nt++)
#pragma unroll
            for (int r = 0; r < 4; r++) acc[mt][nt][r] = 0.0f;

    unsigned smb = sm_u32(sm);
    auto issue = [&](int s, int i) {
        unsigned ab = smb + s * B_ST * 8;
        unsigned mb = ab + 8 * 132 * 8;
#pragma unroll
        for (int t = 0; t < 2; t++) {
            int id = tid + t * 256;
            int jr = id >> 6, mp = (id & 63) * 2;
            cp16g(ab + (jr * 132 + mp) * 8,
                  g_XQ + ((size_t)bb * 128 + 8 * i + jr) * SEQ + m0 + mp);
            cp16g(mb + (jr * 132 + mp) * 8,
                  g_MQ + (size_t)(8 * i + jr) * DIM + cCol * 128 + mp);
        }
        CP_COMMIT();
    };

    const int NT = 16;
    issue(0, 0);
    issue(1, 1);

    for (int i = 0; i < NT; i++) {
        if (i + 1 < NT) CP_WAIT1(); else CP_WAIT0();
        __syncthreads();
        if (i + 2 < NT) issue((i + 2) % 3, i + 2);

        const uint2* A_s = sm + (i % 3) * B_ST;
        const uint2* M_s = A_s + 8 * 132;
#pragma unroll
        for (int gl = 0; gl < 2; gl++) {
            int jb = gl * 4 + tig;
            uint2 va[4], vb[4], w[4];
#pragma unroll
            for (int mt = 0; mt < 4; mt++) {
                int row = wm * 64 + mt * 16 + gid;
                va[mt] = A_s[jb * 132 + row];
                vb[mt] = A_s[jb * 132 + row + 8];
            }
#pragma unroll
            for (int nt = 0; nt < 4; nt++)
                w[nt] = M_s[jb * 132 + wn * 32 + nt * 8 + gid];
#pragma unroll
            for (int mt = 0; mt < 4; mt++)
#pragma unroll
                for (int nt = 0; nt < 4; nt++)
                    mma_f16(acc[mt][nt], va[mt].x, vb[mt].x, va[mt].y, vb[mt].y,
                            w[nt].x, w[nt].y);
        }
    }

    // epilogue: write G quads (nt pairs provide the +8 partners)
#pragma unroll
    for (int mt = 0; mt < 4; mt++)
#pragma unroll
        for (int ntp = 0; ntp < 4; ntp += 2) {
            int g = cCol * 8 + wn * 2 + (ntp >> 1);
            int r = wm * 64 + mt * 16 + gid;
            size_t base = ((size_t)bb * 128 + g * 4 + tig) * SEQ + m0;
            g_GQ[base + r] = packq(acc[mt][ntp][0], acc[mt][ntp][1],
                                   acc[mt][ntp + 1][0], acc[mt][ntp + 1][1]);
            g_GQ[base + r + 8] = packq(acc[mt][ntp][2], acc[mt][ntp][3],
                                       acc[mt][ntp + 1][2], acc[mt][ntp + 1][3]);
        }
}

// ---------------------------------------------------------------------------
// Kernel C: per (batch, half): S = G_half @ X_b^T (fp16 mma, quads, BK=32),
// row softmax, colsum(attn) -> w, y = w @ X_b.  512 thr = 16 warps (4x4).
// ---------------------------------------------------------------------------
#define C_ST 3136   // b64 per stage: G 8*132 + X 8*260
__global__ void __launch_bounds__(512) attn_kernel(float* __restrict__ Y2)
{
    uint2* sm = (uint2*)dynsmem;
    float* red  = dynsmem + 3 * C_ST * 2;      // [128][4]
    float* wcol = red + 128 * 4;               // [4][256]
    float* w_s  = wcol + 4 * 256;              // [256]

    int bx   = blockIdx.x;         // 0..1023
    int b    = bx >> 1;
    int half = bx & 1;
    int tid  = threadIdx.x;
    int warp = tid >> 5, lane = tid & 31;
    int wm = warp >> 2, wn = warp & 3;   // 4 x 4
    int gid = lane >> 2, tig = lane & 3;

    float acc[2][8][4];
#pragma unroll
    for (int mt = 0; mt < 2; mt++)
#pragma unroll
        for (int nt = 0; nt < 8; nt++)
#pragma unroll
            for (int r = 0; r < 4; r++) acc[mt][nt][r] = 0.0f;

    unsigned smb = sm_u32(sm);
    auto issue = [&](int s, int i) {
        unsigned gb = smb + s * C_ST * 8;
        unsigned xb = gb + 8 * 132 * 8;
        {
            int jr = tid >> 6, mp = (tid & 63) * 2;
            cp16g(gb + (jr * 132 + mp) * 8,
                  g_GQ + ((size_t)b * 128 + 8 * i + jr) * SEQ + half * 128 + mp);
        }
#pragma unroll
        for (int t = 0; t < 2; t++) {
            int id = tid + t * 512;
            int jr = id >> 7, mp = (id & 127) * 2;
            cp16g(xb + (jr * 260 + mp) * 8,
                  g_XQ + ((size_t)b * 128 + 8 * i + jr) * SEQ + mp);
        }
        CP_COMMIT();
    };

    const int NT = 16;
    issue(0, 0);
    issue(1, 1);

    for (int i = 0; i < NT; i++) {
        if (i + 1 < NT) CP_WAIT1(); else CP_WAIT0();
        __syncthreads();
        if (i + 2 < NT) issue((i + 2) % 3, i + 2);

        const uint2* G_s = sm + (i % 3) * C_ST;
        const uint2* X_s = G_s + 8 * 132;
#pragma unroll
        for (int gl = 0; gl < 2; gl++) {
            int jb = gl * 4 + tig;
            uint2 va[2], vb[2], w[8];
#pragma unroll
            for (int mt = 0; mt < 2; mt++) {
                int row = wm * 32 + mt * 16 + gid;
                va[mt] = G_s[jb * 132 + row];
                vb[mt] = G_s[jb * 132 + row + 8];
            }
#pragma unroll
            for (int nt = 0; nt < 8; nt++)
                w[nt] = X_s[jb * 260 + wn * 64 + nt * 8 + gid];
#pragma unroll
            for (int mt = 0; mt < 2; mt++)
#pragma unroll
                for (int nt = 0; nt < 8; nt++)
                    mma_f16(acc[mt][nt], va[mt].x, vb[mt].x, va[mt].y, vb[mt].y,
                            w[nt].x, w[nt].y);
        }
    }
    __syncthreads();

    // ---------------- softmax epilogue ----------------
    float rm[2][2];
#pragma unroll
    for (int mt = 0; mt < 2; mt++) {
        float m0 = -1e30f, m1 = -1e30f;
#pragma unroll
        for (int nt = 0; nt < 8; nt++) {
            m0 = fmaxf(m0, fmaxf(acc[mt][nt][0], acc[mt][nt][1]));
            m1 = fmaxf(m1, fmaxf(acc[mt][nt][2], acc[mt][nt][3]));
        }
        m0 = fmaxf(m0, __shfl_xor_sync(0xffffffffu, m0, 1));
        m0 = fmaxf(m0, __shfl_xor_sync(0xffffffffu, m0, 2));
        m1 = fmaxf(m1, __shfl_xor_sync(0xffffffffu, m1, 1));
        m1 = fmaxf(m1, __shfl_xor_sync(0xffffffffu, m1, 2));
        rm[mt][0] = m0; rm[mt][1] = m1;
    }
    if (tig == 0) {
#pragma unroll
        for (int mt = 0; mt < 2; mt++) {
            red[(wm * 32 + mt * 16 + gid) * 4 + wn]     = rm[mt][0];
            red[(wm * 32 + mt * 16 + gid + 8) * 4 + wn] = rm[mt][1];
        }
    }
    __syncthreads();
#pragma unroll
    for (int mt = 0; mt < 2; mt++) {
        int r0 = (wm * 32 + mt * 16 + gid) * 4;
        int r1 = r0 + 32;
        rm[mt][0] = fmaxf(fmaxf(red[r0], red[r0 + 1]), fmaxf(red[r0 + 2], red[r0 + 3]));
        rm[mt][1] = fmaxf(fmaxf(red[r1], red[r1 + 1]), fmaxf(red[r1 + 2], red[r1 + 3]));
    }
    __syncthreads();

    float rs[2][2];
#pragma unroll
    for (int mt = 0; mt < 2; mt++) {
        float s0 = 0.0f, s1 = 0.0f;
#pragma unroll
        for (int nt = 0; nt < 8; nt++) {
            acc[mt][nt][0] = __expf(acc[mt][nt][0] - rm[mt][0]);
            acc[mt][nt][1] = __expf(acc[mt][nt][1] - rm[mt][0]);
            acc[mt][nt][2] = __expf(acc[mt][nt][2] - rm[mt][1]);
            acc[mt][nt][3] = __expf(acc[mt][nt][3] - rm[mt][1]);
            s0 += acc[mt][nt][0] + acc[mt][nt][1];
            s1 += acc[mt][nt][2] + acc[mt][nt][3];
        }
        s0 += __shfl_xor_sync(0xffffffffu, s0, 1);
        s0 += __shfl_xor_sync(0xffffffffu, s0, 2);
        s1 += __shfl_xor_sync(0xffffffffu, s1, 1);
        s1 += __shfl_xor_sync(0xffffffffu, s1, 2);
        rs[mt][0] = s0; rs[mt][1] = s1;
    }
    if (tig == 0) {
#pragma unroll
        for (int mt = 0; mt < 2; mt++) {
            red[(wm * 32 + mt * 16 + gid) * 4 + wn]     = rs[mt][0];
            red[(wm * 32 + mt * 16 + gid + 8) * 4 + wn] = rs[mt][1];
        }
    }
    __syncthreads();
#pragma unroll
    for (int mt = 0; mt < 2; mt++) {
        int r0 = (wm * 32 + mt * 16 + gid) * 4;
        int r1 = r0 + 32;
        rs[mt][0] = 1.0f / (red[r0] + red[r0 + 1] + red[r0 + 2] + red[r0 + 3]);
        rs[mt][1] = 1.0f / (red[r1] + red[r1 + 1] + red[r1 + 2] + red[r1 + 3]);
    }

    float cp[8][2];
#pragma unroll
    for (int nt = 0; nt < 8; nt++) {
        cp[nt][0] = acc[0][nt][0] * rs[0][0] + acc[0][nt][2] * rs[0][1]
                  + acc[1][nt][0] * rs[1][0] + acc[1][nt][2] * rs[1][1];
        cp[nt][1] = acc[0][nt][1] * rs[0][0] + acc[0][nt][3] * rs[0][1]
                  + acc[1][nt][1] * rs[1][0] + acc[1][nt][3] * rs[1][1];
    }
#pragma unroll
    for (int nt = 0; nt < 8; nt++) {
#pragma unroll
        for (int o = 4; o < 32; o <<= 1) {
            cp[nt][0] += __shfl_xor_sync(0xffffffffu, cp[nt][0], o);
            cp[nt][1] += __shfl_xor_sync(0xffffffffu, cp[nt][1], o);
        }
    }
    if (gid == 0) {
#pragma unroll
        for (int nt = 0; nt < 8; nt++) {
            wcol[wm * 256 + wn * 64 + nt * 8 + 2 * tig]     = cp[nt][0];
            wcol[wm * 256 + wn * 64 + nt * 8 + 2 * tig + 1] = cp[nt][1];
        }
    }
    __syncthreads();
    if (tid < 256)
        w_s[tid] = wcol[tid] + wcol[256 + tid] + wcol[512 + tid] + wcol[768 + tid];
    __syncthreads();

    // y_part[d] = sum_m w_s[m] * X_b[m, d]   (from quad-packed XQ)
    {
        int d = tid;
        int g = d >> 4, rr = d & 15;
        int j = (rr >> 1) & 3;
        int hidx = ((rr >> 3) << 1) | (rr & 1);
        const uint2* Xq = g_XQ + ((size_t)b * 128 + g * 4 + j) * SEQ;
        float y = 0.0f;
#pragma unroll 4
        for (int m = 0; m < SEQ; m++) {
            uint2 qv = Xq[m];
            unsigned wv = (hidx & 2) ? qv.y : qv.x;
            __half2 h2 = *reinterpret_cast<__half2*>(&wv);
            float xv = __half2float((hidx & 1) ? __high2half(h2) : __low2half(h2));
            y = fmaf(w_s[m], xv, y);
        }
        Y2[(size_t)bx * DIM + d] = y;
    }
}

// ---------------------------------------------------------------------------
// Kernel D: merged = Y @ Wv, Y[b] = Y2[2b] + Y2[2b+1].  (unchanged, fp32)
// ---------------------------------------------------------------------------
__global__ void __launch_bounds__(256) final_gemm_kernel(const float* __restrict__ Wv,
                                                         float* __restrict__ out)
{
    __shared__ float As[32][68];
    __shared__ float Bs[32][68];
    int tid  = threadIdx.x;
    int batch0 = blockIdx.y * 64;
    int col0   = blockIdx.x * 64;

    int ar = tid >> 2, akk = (tid & 3) * 8;
    int bk = tid >> 3, bn = (tid & 7) * 8;
    int tr = tid >> 4, tc = tid & 15;

    float acc[4][4];
#pragma unroll
    for (int i = 0; i < 4; i++)
#pragma unroll
        for (int j = 0; j < 4; j++) acc[i][j] = 0.0f;

    for (int kt = 0; kt < DIM; kt += 32) {
        {
            const float* y0 = g_Y2 + (size_t)(2 * (batch0 + ar)) * DIM + kt + akk;
            const float* y1 = y0 + DIM;
            float4 a0 = *(const float4*)y0;
            float4 a1 = *(const float4*)(y0 + 4);
            float4 b0 = *(const float4*)y1;
            float4 b1 = *(const float4*)(y1 + 4);
            As[akk + 0][ar] = a0.x + b0.x;
            As[akk + 1][ar] = a0.y + b0.y;
            As[akk + 2][ar] = a0.z + b0.z;
            As[akk + 3][ar] = a0.w + b0.w;
            As[akk + 4][ar] = a1.x + b1.x;
            As[akk + 5][ar] = a1.y + b1.y;
            As[akk + 6][ar] = a1.z + b1.z;
            As[akk + 7][ar] = a1.w + b1.w;
        }
        {
            const float* wp = Wv + (size_t)(kt + bk) * DIM + col0 + bn;
            *(float4*)(&Bs[bk][bn])     = *(const float4*)wp;
            *(float4*)(&Bs[bk][bn + 4]) = *(const float4*)(wp + 4);
        }
        __syncthreads();
#pragma unroll
        for (int k = 0; k < 32; k++) {
            float4 ra = *(const float4*)(&As[k][tr * 4]);
            float4 rb = *(const float4*)(&Bs[k][tc * 4]);
            float a[4] = {ra.x, ra.y, ra.z, ra.w};
            float b[4] = {rb.x, rb.y, rb.z, rb.w};
#pragma unroll
            for (int i = 0; i < 4; i++)
#pragma unroll
                for (int j = 0; j < 4; j++)
                    acc[i][j] += a[i] * b[j];
        }
        __syncthreads();
    }
#pragma unroll
    for (int i = 0; i < 4; i++) {
        float* op = out + (size_t)(batch0 + tr * 4 + i) * DIM + col0 + tc * 4;
        *(float4*)op = make_float4(acc[i][0], acc[i][1], acc[i][2], acc[i][3]);
    }
}

// ---------------------------------------------------------------------------
// Launch
// ---------------------------------------------------------------------------
extern "C" void kernel_launch(void* const* d_in, const int* in_sizes, int n_in,
                              void* d_out, int out_size)
{
    const float* X  = (const float*)d_in[0];   // [512,256,512]
    const float* Wq = (const float*)d_in[1];   // [512,512]
    const float* Wk = (const float*)d_in[2];
    const float* Wv = (const float*)d_in[3];
    float* out = (float*)d_out;                // [512,512]

    float* Y2;
    cudaGetSymbolAddress((void**)&Y2, g_Y2);

    const int smemB = 3 * B_ST * 8;                     // 50688 B
    const int smemC = 3 * C_ST * 8 + 1792 * 4;          // 82432 B
    cudaFuncSetAttribute(gemm_G_kernel, cudaFuncAttributeMaxDynamicSharedMemorySize, smemB);
    cudaFuncSetAttribute(attn_kernel,   cudaFuncAttributeMaxDynamicSharedMemorySize, smemC);

    // X -> quad-packed fp16
    x2h_kernel<<<dim3(8, 4, 512), 256>>>(X);
    // A: MQ = quad-pack(norm * Wq @ Wk^T)
    wqwk_kernel<<<dim3(8, 8), 256>>>(Wq, Wk);
    // B: GQ = quad-pack(X @ M)  (fp16 mma.sync)
    gemm_G_kernel<<<dim3(4, 1024), 256, smemB>>>();
    // C: fused scores/softmax/colsum/y per (batch, half)
    attn_kernel<<<1024, 512, smemC>>>(Y2);
    // D: merged = (Y2[2b]+Y2[2b+1]) @ Wv
    final_gemm_kernel<<<dim3(8, 8), 256>>>(Wv, out);
}

// round 14
// speedup vs baseline: 2.6904x; 1.1286x over previous
#include <cuda_runtime.h>
#include <cuda_bf16.h>
#include <cuda_fp16.h>
#include <math.h>

// Problem shape
#define BATCH 512
#define SEQ   256
#define DIM   512
#define NORM  0.044194173824159216f   // 1/sqrt(512)

// Quad-packed fp16 operand layout:
//   Q[row][m], row = kgroup*4 + j, packs halves (v[m][16g+2j], [+1], [+8], [+9])
//   -> b-fragment = 1 LDS.64, a-fragment = 2 LDS.64 (row, row+8)
__device__ uint2 g_MQ[128 * DIM];                     // M quads: [kg*4+j][n]
__device__ uint2 g_XQ[(size_t)BATCH * 128 * SEQ];     // X quads: [b*128 + kg*4+j][m]
__device__ uint2 g_GQ[(size_t)BATCH * 128 * SEQ];     // G quads: [b*128 + ng*4+j][m]
__device__ float g_Y2[(size_t)BATCH * 2 * DIM];       // per-half y contributions

extern __shared__ float dynsmem[];

// ---------------------------------------------------------------------------
// helpers
// ---------------------------------------------------------------------------
__device__ __forceinline__ void cp16g(unsigned sa, const void* g) {
    asm volatile("cp.async.cg.shared.global [%0], [%1], 16;" :: "r"(sa), "l"(g));
}
#define CP_COMMIT() asm volatile("cp.async.commit_group;")
#define CP_WAIT1()  asm volatile("cp.async.wait_group 1;")
#define CP_WAIT0()  asm volatile("cp.async.wait_group 0;")

__device__ __forceinline__ void mma_f16(float c[4],
                                        unsigned a0, unsigned a1, unsigned a2, unsigned a3,
                                        unsigned b0, unsigned b1) {
    asm("mma.sync.aligned.m16n8k16.row.col.f32.f16.f16.f32 "
        "{%0,%1,%2,%3}, {%4,%5,%6,%7}, {%8,%9}, {%0,%1,%2,%3};"
        : "+f"(c[0]), "+f"(c[1]), "+f"(c[2]), "+f"(c[3])
        : "r"(a0), "r"(a1), "r"(a2), "r"(a3), "r"(b0), "r"(b1));
}
__device__ __forceinline__ unsigned sm_u32(const void* p) {
    return (unsigned)__cvta_generic_to_shared(p);
}
__device__ __forceinline__ uint2 packq(float a, float b, float c, float d) {
    __half2 lo = __floats2half2_rn(a, b);
    __half2 hi = __floats2half2_rn(c, d);
    uint2 r;
    r.x = *(unsigned*)&lo;
    r.y = *(unsigned*)&hi;
    return r;
}

// ---------------------------------------------------------------------------
// Kernel X2H: X (fp32) -> g_XQ quad-packed fp16.
// grid (8 ktile, 4 mtile, 512 batch), 256 thr, 64x64 tile via smem.
// ---------------------------------------------------------------------------
__global__ void __launch_bounds__(256) x2h_kernel(const float* __restrict__ X)
{
    __shared__ float s[64][65];
    int tid = threadIdx.x;
    int ktile = blockIdx.x, mtile = blockIdx.y, b = blockIdx.z;

    int r = tid >> 2, c4 = (tid & 3) * 16;
    const float* src = X + ((size_t)b * SEQ + mtile * 64 + r) * DIM + ktile * 64 + c4;
#pragma unroll
    for (int i = 0; i < 4; i++) {
        float4 v = *(const float4*)(src + i * 4);
        s[r][c4 + i * 4 + 0] = v.x;
        s[r][c4 + i * 4 + 1] = v.y;
        s[r][c4 + i * 4 + 2] = v.z;
        s[r][c4 + i * 4 + 3] = v.w;
    }
    __syncthreads();

    int q = tid >> 4, g = q >> 2, j = q & 3;
    int ml = (tid & 15) * 4;
    int kb = g * 16 + 2 * j;
    size_t row = (size_t)b * 128 + (ktile * 4 + g) * 4 + j;
    uint2* dst = g_XQ + row * SEQ + mtile * 64 + ml;
#pragma unroll
    for (int i = 0; i < 4; i++)
        dst[i] = packq(s[ml + i][kb], s[ml + i][kb + 1],
                       s[ml + i][kb + 8], s[ml + i][kb + 9]);
}

// ---------------------------------------------------------------------------
// Kernel A: M = norm * Wq @ Wk^T -> g_MQ quad-packed.  64x64 tiles, grid 8x8.
// ---------------------------------------------------------------------------
__global__ void __launch_bounds__(256) wqwk_kernel(const float* __restrict__ Wq,
                                                   const float* __restrict__ Wk)
{
    __shared__ float As[32][68];   // [e][row]
    __shared__ float Bs[32][68];   // [e][col]
    __shared__ float Ms[64][65];   // staging for quad pack
    int tid = threadIdx.x;
    int row0 = blockIdx.y * 64;    // k-dim of M
    int col0 = blockIdx.x * 64;    // n-dim of M

    int sr = tid >> 2, se = (tid & 3) * 8;
    int tr = tid >> 4, tc = tid & 15;

    float acc[4][4];
#pragma unroll
    for (int i = 0; i < 4; i++)
#pragma unroll
        for (int jj = 0; jj < 4; jj++) acc[i][jj] = 0.0f;

    for (int kt = 0; kt < DIM; kt += 32) {
        float4 q0 = *(const float4*)(Wq + (size_t)(row0 + sr) * DIM + kt + se);
        float4 q1 = *(const float4*)(Wq + (size_t)(row0 + sr) * DIM + kt + se + 4);
        float4 k0 = *(const float4*)(Wk + (size_t)(col0 + sr) * DIM + kt + se);
        float4 k1 = *(const float4*)(Wk + (size_t)(col0 + sr) * DIM + kt + se + 4);
        As[se + 0][sr] = q0.x; As[se + 1][sr] = q0.y;
        As[se + 2][sr] = q0.z; As[se + 3][sr] = q0.w;
        As[se + 4][sr] = q1.x; As[se + 5][sr] = q1.y;
        As[se + 6][sr] = q1.z; As[se + 7][sr] = q1.w;
        Bs[se + 0][sr] = k0.x; Bs[se + 1][sr] = k0.y;
        Bs[se + 2][sr] = k0.z; Bs[se + 3][sr] = k0.w;
        Bs[se + 4][sr] = k1.x; Bs[se + 5][sr] = k1.y;
        Bs[se + 6][sr] = k1.z; Bs[se + 7][sr] = k1.w;
        __syncthreads();
#pragma unroll
        for (int k = 0; k < 32; k++) {
            float4 ra = *(const float4*)(&As[k][tr * 4]);
            float4 rb = *(const float4*)(&Bs[k][tc * 4]);
            float a[4] = {ra.x, ra.y, ra.z, ra.w};
            float b[4] = {rb.x, rb.y, rb.z, rb.w};
#pragma unroll
            for (int i = 0; i < 4; i++)
#pragma unroll
                for (int jj = 0; jj < 4; jj++)
                    acc[i][jj] += a[i] * b[jj];
        }
        __syncthreads();
    }
    // stage into Ms [local k][local n]
#pragma unroll
    for (int i = 0; i < 4; i++)
#pragma unroll
        for (int jj = 0; jj < 4; jj++)
            Ms[tr * 4 + i][tc * 4 + jj] = acc[i][jj] * NORM;
    __syncthreads();

    // quad pack -> g_MQ
    int q = tid >> 4, g = q >> 2, j = q & 3;
    int nl = (tid & 15) * 4;
    int kb = g * 16 + 2 * j;
    size_t rowI = (size_t)((row0 >> 4) + g) * 4 + j;
#pragma unroll
    for (int i = 0; i < 4; i++) {
        int n = nl + i;
        g_MQ[rowI * DIM + col0 + n] = packq(Ms[kb][n], Ms[kb + 1][n],
                                            Ms[kb + 8][n], Ms[kb + 9][n]);
    }
}

// ---------------------------------------------------------------------------
// Kernel B: G = X @ M via fp16 mma (k16), all operands quad-packed.
// CTA 128x128, BK=32, 256 thr = 8 warps (2x4), warp tile 64x32.
// 3-stage cp.async; mainloop FULLY UNROLLED (stage index compile-time).
// ---------------------------------------------------------------------------
#define B_ST 2112   // b64 per stage: A 8*132 + M 8*132
__global__ void __launch_bounds__(256) gemm_G_kernel()
{
    uint2* sm = (uint2*)dynsmem;
    int tid = threadIdx.x;
    int cCol = blockIdx.x;            // 0..3
    int cRow = blockIdx.y;            // 0..1023
    int warp = tid >> 5, lane = tid & 31;
    int wm = warp >> 2, wn = warp & 3;
    int gid = lane >> 2, tig = lane & 3;
    int bb = cRow >> 1, m0 = (cRow & 1) * 128;

    float acc[4][4][4];
#pragma unroll
    for (int mt = 0; mt < 4; mt++)
#pragma unroll
        for (int nt = 0; nt < 4; nt++)
#pragma unroll
            for (int r = 0; r < 4; r++) acc[mt][nt][r] = 0.0f;

    unsigned smb = sm_u32(sm);
    // hoisted staging sub-addresses (tid-only)
    int jr0 = tid >> 6, mp0 = (tid & 63) * 2;
    int jr1 = (tid + 256) >> 6, mp1 = ((tid + 256) & 63) * 2;
    const uint2* XQb = g_XQ + (size_t)bb * 128 * SEQ + m0;
    const uint2* MQb = g_MQ + cCol * 128;

    auto issue = [&](int s, int i) {
        unsigned ab = smb + s * B_ST * 8;
        unsigned mb = ab + 8 * 132 * 8;
        cp16g(ab + (jr0 * 132 + mp0) * 8, XQb + (size_t)(8 * i + jr0) * SEQ + mp0);
        cp16g(mb + (jr0 * 132 + mp0) * 8, MQb + (size_t)(8 * i + jr0) * DIM + mp0);
        cp16g(ab + (jr1 * 132 + mp1) * 8, XQb + (size_t)(8 * i + jr1) * SEQ + mp1);
        cp16g(mb + (jr1 * 132 + mp1) * 8, MQb + (size_t)(8 * i + jr1) * DIM + mp1);
        CP_COMMIT();
    };

    const int NT = 16;
    issue(0, 0);
    issue(1, 1);

#pragma unroll
    for (int i = 0; i < NT; i++) {
        if (i + 1 < NT) CP_WAIT1(); else CP_WAIT0();
        __syncthreads();
        if (i + 2 < NT) issue((i + 2) % 3, i + 2);

        const uint2* A_s = sm + (i % 3) * B_ST;
        const uint2* M_s = A_s + 8 * 132;
#pragma unroll
        for (int gl = 0; gl < 2; gl++) {
            int jb = gl * 4 + tig;
            uint2 va[4], vb[4], w[4];
#pragma unroll
            for (int mt = 0; mt < 4; mt++) {
                int row = wm * 64 + mt * 16 + gid;
                va[mt] = A_s[jb * 132 + row];
                vb[mt] = A_s[jb * 132 + row + 8];
            }
#pragma unroll
            for (int nt = 0; nt < 4; nt++)
                w[nt] = M_s[jb * 132 + wn * 32 + nt * 8 + gid];
#pragma unroll
            for (int mt = 0; mt < 4; mt++)
#pragma unroll
                for (int nt = 0; nt < 4; nt++)
                    mma_f16(acc[mt][nt], va[mt].x, vb[mt].x, va[mt].y, vb[mt].y,
                            w[nt].x, w[nt].y);
        }
    }

    // epilogue: write G quads (nt pairs provide the +8 partners)
#pragma unroll
    for (int mt = 0; mt < 4; mt++)
#pragma unroll
        for (int ntp = 0; ntp < 4; ntp += 2) {
            int g = cCol * 8 + wn * 2 + (ntp >> 1);
            int r = wm * 64 + mt * 16 + gid;
            size_t base = ((size_t)bb * 128 + g * 4 + tig) * SEQ + m0;
            g_GQ[base + r] = packq(acc[mt][ntp][0], acc[mt][ntp][1],
                                   acc[mt][ntp + 1][0], acc[mt][ntp + 1][1]);
            g_GQ[base + r + 8] = packq(acc[mt][ntp][2], acc[mt][ntp][3],
                                       acc[mt][ntp + 1][2], acc[mt][ntp + 1][3]);
        }
}

// ---------------------------------------------------------------------------
// Kernel C: per (batch, half): S = G_half @ X_b^T (fp16 mma, quads, BK=32),
// row softmax, colsum(attn) -> w, y = w @ X_b.  512 thr = 16 warps (4x4).
// Mainloop FULLY UNROLLED; quad-native y epilogue.
// ---------------------------------------------------------------------------
#define C_ST 3136   // b64 per stage: G 8*132 + X 8*260
__global__ void __launch_bounds__(512) attn_kernel(float* __restrict__ Y2)
{
    uint2* sm = (uint2*)dynsmem;
    float* red  = dynsmem + 3 * C_ST * 2;      // [128][4]
    float* wcol = red + 128 * 4;               // [4][256]
    float* w_s  = wcol + 4 * 256;              // [256]

    int bx   = blockIdx.x;         // 0..1023
    int b    = bx >> 1;
    int half = bx & 1;
    int tid  = threadIdx.x;
    int warp = tid >> 5, lane = tid & 31;
    int wm = warp >> 2, wn = warp & 3;   // 4 x 4
    int gid = lane >> 2, tig = lane & 3;

    float acc[2][8][4];
#pragma unroll
    for (int mt = 0; mt < 2; mt++)
#pragma unroll
        for (int nt = 0; nt < 8; nt++)
#pragma unroll
            for (int r = 0; r < 4; r++) acc[mt][nt][r] = 0.0f;

    unsigned smb = sm_u32(sm);
    int gjr = tid >> 6, gmp = (tid & 63) * 2;
    int xjr0 = tid >> 7, xmp0 = (tid & 127) * 2;
    int xjr1 = (tid + 512) >> 7, xmp1 = ((tid + 512) & 127) * 2;
    const uint2* GQb = g_GQ + (size_t)b * 128 * SEQ + half * 128;
    const uint2* XQb = g_XQ + (size_t)b * 128 * SEQ;

    auto issue = [&](int s, int i) {
        unsigned gb = smb + s * C_ST * 8;
        unsigned xb = gb + 8 * 132 * 8;
        cp16g(gb + (gjr * 132 + gmp) * 8,  GQb + (size_t)(8 * i + gjr) * SEQ + gmp);
        cp16g(xb + (xjr0 * 260 + xmp0) * 8, XQb + (size_t)(8 * i + xjr0) * SEQ + xmp0);
        cp16g(xb + (xjr1 * 260 + xmp1) * 8, XQb + (size_t)(8 * i + xjr1) * SEQ + xmp1);
        CP_COMMIT();
    };

    const int NT = 16;
    issue(0, 0);
    issue(1, 1);

#pragma unroll
    for (int i = 0; i < NT; i++) {
        if (i + 1 < NT) CP_WAIT1(); else CP_WAIT0();
        __syncthreads();
        if (i + 2 < NT) issue((i + 2) % 3, i + 2);

        const uint2* G_s = sm + (i % 3) * C_ST;
        const uint2* X_s = G_s + 8 * 132;
#pragma unroll
        for (int gl = 0; gl < 2; gl++) {
            int jb = gl * 4 + tig;
            uint2 va[2], vb[2], w[8];
#pragma unroll
            for (int mt = 0; mt < 2; mt++) {
                int row = wm * 32 + mt * 16 + gid;
                va[mt] = G_s[jb * 132 + row];
                vb[mt] = G_s[jb * 132 + row + 8];
            }
#pragma unroll
            for (int nt = 0; nt < 8; nt++)
                w[nt] = X_s[jb * 260 + wn * 64 + nt * 8 + gid];
#pragma unroll
            for (int mt = 0; mt < 2; mt++)
#pragma unroll
                for (int nt = 0; nt < 8; nt++)
                    mma_f16(acc[mt][nt], va[mt].x, vb[mt].x, va[mt].y, vb[mt].y,
                            w[nt].x, w[nt].y);
        }
    }
    __syncthreads();

    // ---------------- softmax epilogue ----------------
    float rm[2][2];
#pragma unroll
    for (int mt = 0; mt < 2; mt++) {
        float m0 = -1e30f, m1 = -1e30f;
#pragma unroll
        for (int nt = 0; nt < 8; nt++) {
            m0 = fmaxf(m0, fmaxf(acc[mt][nt][0], acc[mt][nt][1]));
            m1 = fmaxf(m1, fmaxf(acc[mt][nt][2], acc[mt][nt][3]));
        }
        m0 = fmaxf(m0, __shfl_xor_sync(0xffffffffu, m0, 1));
        m0 = fmaxf(m0, __shfl_xor_sync(0xffffffffu, m0, 2));
        m1 = fmaxf(m1, __shfl_xor_sync(0xffffffffu, m1, 1));
        m1 = fmaxf(m1, __shfl_xor_sync(0xffffffffu, m1, 2));
        rm[mt][0] = m0; rm[mt][1] = m1;
    }
    if (tig == 0) {
#pragma unroll
        for (int mt = 0; mt < 2; mt++) {
            red[(wm * 32 + mt * 16 + gid) * 4 + wn]     = rm[mt][0];
            red[(wm * 32 + mt * 16 + gid + 8) * 4 + wn] = rm[mt][1];
        }
    }
    __syncthreads();
#pragma unroll
    for (int mt = 0; mt < 2; mt++) {
        int r0 = (wm * 32 + mt * 16 + gid) * 4;
        int r1 = r0 + 32;
        rm[mt][0] = fmaxf(fmaxf(red[r0], red[r0 + 1]), fmaxf(red[r0 + 2], red[r0 + 3]));
        rm[mt][1] = fmaxf(fmaxf(red[r1], red[r1 + 1]), fmaxf(red[r1 + 2], red[r1 + 3]));
    }
    __syncthreads();

    float rs[2][2];
#pragma unroll
    for (int mt = 0; mt < 2; mt++) {
        float s0 = 0.0f, s1 = 0.0f;
#pragma unroll
        for (int nt = 0; nt < 8; nt++) {
            acc[mt][nt][0] = __expf(acc[mt][nt][0] - rm[mt][0]);
            acc[mt][nt][1] = __expf(acc[mt][nt][1] - rm[mt][0]);
            acc[mt][nt][2] = __expf(acc[mt][nt][2] - rm[mt][1]);
            acc[mt][nt][3] = __expf(acc[mt][nt][3] - rm[mt][1]);
            s0 += acc[mt][nt][0] + acc[mt][nt][1];
            s1 += acc[mt][nt][2] + acc[mt][nt][3];
        }
        s0 += __shfl_xor_sync(0xffffffffu, s0, 1);
        s0 += __shfl_xor_sync(0xffffffffu, s0, 2);
        s1 += __shfl_xor_sync(0xffffffffu, s1, 1);
        s1 += __shfl_xor_sync(0xffffffffu, s1, 2);
        rs[mt][0] = s0; rs[mt][1] = s1;
    }
    if (tig == 0) {
#pragma unroll
        for (int mt = 0; mt < 2; mt++) {
            red[(wm * 32 + mt * 16 + gid) * 4 + wn]     = rs[mt][0];
            red[(wm * 32 + mt * 16 + gid + 8) * 4 + wn] = rs[mt][1];
        }
    }
    __syncthreads();
#pragma unroll
    for (int mt = 0; mt < 2; mt++) {
        int r0 = (wm * 32 + mt * 16 + gid) * 4;
        int r1 = r0 + 32;
        rs[mt][0] = 1.0f / (red[r0] + red[r0 + 1] + red[r0 + 2] + red[r0 + 3]);
        rs[mt][1] = 1.0f / (red[r1] + red[r1 + 1] + red[r1 + 2] + red[r1 + 3]);
    }

    float cp[8][2];
#pragma unroll
    for (int nt = 0; nt < 8; nt++) {
        cp[nt][0] = acc[0][nt][0] * rs[0][0] + acc[0][nt][2] * rs[0][1]
                  + acc[1][nt][0] * rs[1][0] + acc[1][nt][2] * rs[1][1];
        cp[nt][1] = acc[0][nt][1] * rs[0][0] + acc[0][nt][3] * rs[0][1]
                  + acc[1][nt][1] * rs[1][0] + acc[1][nt][3] * rs[1][1];
    }
#pragma unroll
    for (int nt = 0; nt < 8; nt++) {
#pragma unroll
        for (int o = 4; o < 32; o <<= 1) {
            cp[nt][0] += __shfl_xor_sync(0xffffffffu, cp[nt][0], o);
            cp[nt][1] += __shfl_xor_sync(0xffffffffu, cp[nt][1], o);
        }
    }
    if (gid == 0) {
#pragma unroll
        for (int nt = 0; nt < 8; nt++) {
            wcol[wm * 256 + wn * 64 + nt * 8 + 2 * tig]     = cp[nt][0];
            wcol[wm * 256 + wn * 64 + nt * 8 + 2 * tig + 1] = cp[nt][1];
        }
    }
    __syncthreads();
    if (tid < 256)
        w_s[tid] = wcol[tid] + wcol[256 + tid] + wcol[512 + tid] + wcol[768 + tid];
    __syncthreads();

    // ---------------- y epilogue (quad-native) ----------------
    // thread (r = tid>>2, p = tid&3): accumulate float4 for quad-row r over
    // m in [p*64, p*64+64); reduce over p via shfl; p==0 writes 2 float2.
    {
        int r = tid >> 2, p = tid & 3;
        const uint2* Xq = XQb + (size_t)r * SEQ + p * 64;
        const float* wp = w_s + p * 64;
        float4 a = make_float4(0.f, 0.f, 0.f, 0.f);
#pragma unroll 8
        for (int m = 0; m < 64; m++) {
            uint2 qv = Xq[m];
            float wv = wp[m];
            __half2 lo = *reinterpret_cast<__half2*>(&qv.x);
            __half2 hi = *reinterpret_cast<__half2*>(&qv.y);
            float2 flo = __half22float2(lo);
            float2 fhi = __half22float2(hi);
            a.x = fmaf(wv, flo.x, a.x);
            a.y = fmaf(wv, flo.y, a.y);
            a.z = fmaf(wv, fhi.x, a.z);
            a.w = fmaf(wv, fhi.y, a.w);
        }
#pragma unroll
        for (int o = 1; o < 4; o <<= 1) {
            a.x += __shfl_xor_sync(0xffffffffu, a.x, o);
            a.y += __shfl_xor_sync(0xffffffffu, a.y, o);
            a.z += __shfl_xor_sync(0xffffffffu, a.z, o);
            a.w += __shfl_xor_sync(0xffffffffu, a.w, o);
        }
        if (p == 0) {
            int g = r >> 2, j = r & 3;
            int d0 = 16 * g + 2 * j;
            float* yp = Y2 + (size_t)bx * DIM;
            *(float2*)(yp + d0)     = make_float2(a.x, a.y);
            *(float2*)(yp + d0 + 8) = make_float2(a.z, a.w);
        }
    }
}

// ---------------------------------------------------------------------------
// Kernel D: merged = Y @ Wv, Y[b] = Y2[2b] + Y2[2b+1].  (unchanged, fp32)
// ---------------------------------------------------------------------------
__global__ void __launch_bounds__(256) final_gemm_kernel(const float* __restrict__ Wv,
                                                         float* __restrict__ out)
{
    __shared__ float As[32][68];
    __shared__ float Bs[32][68];
    int tid  = threadIdx.x;
    int batch0 = blockIdx.y * 64;
    int col0   = blockIdx.x * 64;

    int ar = tid >> 2, akk = (tid & 3) * 8;
    int bk = tid >> 3, bn = (tid & 7) * 8;
    int tr = tid >> 4, tc = tid & 15;

    float acc[4][4];
#pragma unroll
    for (int i = 0; i < 4; i++)
#pragma unroll
        for (int j = 0; j < 4; j++) acc[i][j] = 0.0f;

    for (int kt = 0; kt < DIM; kt += 32) {
        {
            const float* y0 = g_Y2 + (size_t)(2 * (batch0 + ar)) * DIM + kt + akk;
            const float* y1 = y0 + DIM;
            float4 a0 = *(const float4*)y0;
            float4 a1 = *(const float4*)(y0 + 4);
            float4 b0 = *(const float4*)y1;
            float4 b1 = *(const float4*)(y1 + 4);
            As[akk + 0][ar] = a0.x + b0.x;
            As[akk + 1][ar] = a0.y + b0.y;
            As[akk + 2][ar] = a0.z + b0.z;
            As[akk + 3][ar] = a0.w + b0.w;
            As[akk + 4][ar] = a1.x + b1.x;
            As[akk + 5][ar] = a1.y + b1.y;
            As[akk + 6][ar] = a1.z + b1.z;
            As[akk + 7][ar] = a1.w + b1.w;
        }
        {
            const float* wp = Wv + (size_t)(kt + bk) * DIM + col0 + bn;
            *(float4*)(&Bs[bk][bn])     = *(const float4*)wp;
            *(float4*)(&Bs[bk][bn + 4]) = *(const float4*)(wp + 4);
        }
        __syncthreads();
#pragma unroll
        for (int k = 0; k < 32; k++) {
            float4 ra = *(const float4*)(&As[k][tr * 4]);
            float4 rb = *(const float4*)(&Bs[k][tc * 4]);
            float a[4] = {ra.x, ra.y, ra.z, ra.w};
            float b[4] = {rb.x, rb.y, rb.z, rb.w};
#pragma unroll
            for (int i = 0; i < 4; i++)
#pragma unroll
                for (int j = 0; j < 4; j++)
                    acc[i][j] += a[i] * b[j];
        }
        __syncthreads();
    }
#pragma unroll
    for (int i = 0; i < 4; i++) {
        float* op = out + (size_t)(batch0 + tr * 4 + i) * DIM + col0 + tc * 4;
        *(float4*)op = make_float4(acc[i][0], acc[i][1], acc[i][2], acc[i][3]);
    }
}

// ---------------------------------------------------------------------------
// Launch
// ---------------------------------------------------------------------------
extern "C" void kernel_launch(void* const* d_in, const int* in_sizes, int n_in,
                              void* d_out, int out_size)
{
    const float* X  = (const float*)d_in[0];   // [512,256,512]
    const float* Wq = (const float*)d_in[1];   // [512,512]
    const float* Wk = (const float*)d_in[2];
    const float* Wv = (const float*)d_in[3];
    float* out = (float*)d_out;                // [512,512]

    float* Y2;
    cudaGetSymbolAddress((void**)&Y2, g_Y2);

    const int smemB = 3 * B_ST * 8;                     // 50688 B
    const int smemC = 3 * C_ST * 8 + 1792 * 4;          // 82432 B
    cudaFuncSetAttribute(gemm_G_kernel, cudaFuncAttributeMaxDynamicSharedMemorySize, smemB);
    cudaFuncSetAttribute(attn_kernel,   cudaFuncAttributeMaxDynamicSharedMemorySize, smemC);

    // X -> quad-packed fp16
    x2h_kernel<<<dim3(8, 4, 512), 256>>>(X);
    // A: MQ = quad-pack(norm * Wq @ Wk^T)
    wqwk_kernel<<<dim3(8, 8), 256>>>(Wq, Wk);
    // B: GQ = quad-pack(X @ M)  (fp16 mma.sync)
    gemm_G_kernel<<<dim3(4, 1024), 256, smemB>>>();
    // C: fused scores/softmax/colsum/y per (batch, half)
    attn_kernel<<<1024, 512, smemC>>>(Y2);
    // D: merged = (Y2[2b]+Y2[2b+1]) @ Wv
    final_gemm_kernel<<<dim3(8, 8), 256>>>(Wv, out);
}